// round 12
// baseline (speedup 1.0000x reference)
#include <cuda_runtime.h>
#include <cuda_bf16.h>
#include <cstdint>

#define BB 16
#define CC 128
#define NN 1024
#define KK 9
#define NCH 8            // candidate m-chunks (one per m-block of 128)
#define NPT (BB*NN)      // 16384 points
#define ROW_W 68         // smem row stride in 32-bit words (64 data + 4 pad)

// ---- scratch (device globals; no allocation allowed) ----
__device__ float  g_sq[NPT];
__device__ float  g_u[NPT*CC];
__device__ float  g_v[NPT*CC];
__device__ int    g_idx[NPT*KK];
__device__ float  g_pre[NPT*CC];
__device__ float  g_cd[NCH*KK*NPT];
__device__ int    g_ci[NCH*KK*NPT];
__device__ double g_dsum[CC];
__device__ double g_dsqs[CC];
__device__ float  g_scale[CC];
__device__ float  g_shift[CC];

// warp-level bf16 MMA (PTX ISA 7.0+, compiles on compute_103 -> HMMA)
__device__ __forceinline__ void mma16816(float* c, const uint32_t* a, const uint32_t* b) {
    asm volatile(
        "mma.sync.aligned.m16n8k16.row.col.f32.bf16.bf16.f32 "
        "{%0,%1,%2,%3}, {%4,%5,%6,%7}, {%8,%9}, {%0,%1,%2,%3};"
        : "+f"(c[0]), "+f"(c[1]), "+f"(c[2]), "+f"(c[3])
        : "r"(a[0]), "r"(a[1]), "r"(a[2]), "r"(a[3]), "r"(b[0]), "r"(b[1]));
}

// ---------------- K0 ----------------
__global__ void k_init() {
    int t = threadIdx.x;
    g_dsum[t] = 0.0; g_dsqs[t] = 0.0;
}

// ---------------- K1: per-point sq, u, v (unchanged) ----------------
__global__ void __launch_bounds__(128) k_point(
    const float* __restrict__ x, const float* __restrict__ W1,
    const float* __restrict__ b1)
{
    __shared__ float fs[16*130];
    int t = threadIdx.x;
    int base = blockIdx.x * 16;
    int b = base / NN, n0 = base % NN;
    {
        int p = t & 15, c0 = t >> 4;
        #pragma unroll
        for (int i = 0; i < 16; i++) {
            int c = c0 + i*8;
            fs[p*130 + c] = x[(b*CC + c)*NN + n0 + p];
        }
    }
    __syncthreads();
    if (t < 16) {
        float s = 0.f;
        #pragma unroll 4
        for (int c = 0; c < CC; c++) { float f = fs[t*130+c]; s += f*f; }
        g_sq[base + t] = s;
    }
    int j = t;
    float accU[16], accV[16];
    #pragma unroll
    for (int p = 0; p < 16; p++) { accU[p]=0.f; accV[p]=0.f; }
    for (int c = 0; c < CC; c++) {
        float wa = W1[c*CC + j];
        float wb = W1[(CC+c)*CC + j];
        #pragma unroll
        for (int p = 0; p < 16; p++) {
            float f = fs[p*130 + c];
            accU[p] = fmaf(f, wa, accU[p]);
            accV[p] = fmaf(f, wb, accV[p]);
        }
    }
    float bj = b1[j];
    #pragma unroll
    for (int p = 0; p < 16; p++) {
        g_u[(base+p)*CC + j] = accU[p] + bj;
        g_v[(base+p)*CC + j] = accV[p];
    }
}

// ---------------- K2a: fused tensor gram + per-m-block top-9 ----------------
// CTA: dot tile (n0..+127) x (m0..+127), batch b. 8 warps x 16 n-rows.
// After MMA, rank by key = sq_m - 2*dot (== d2 - sq_n, same order), quad-merge
// via shfl.xor, write 9 candidates per (row, m-block). No dot matrix in DRAM.
__global__ void __launch_bounds__(256) k_gram(const float* __restrict__ x)
{
    extern __shared__ __align__(16) uint32_t sm[];
    uint32_t* SA_HI = sm;
    uint32_t* SA_LO = sm + 128*ROW_W;
    uint32_t* SB_HI = sm + 2*128*ROW_W;
    uint32_t* SB_LO = sm + 3*128*ROW_W;
    float*    sqm   = (float*)(sm + 4*128*ROW_W);   // 128 floats

    int tid = threadIdx.x;
    int b  = blockIdx.z;
    int n0 = blockIdx.x * 128, m0 = blockIdx.y * 128;

    // stage + split: grp 0 loads A rows (n), grp 1 loads B rows (m); coalesced
    {
        int grp = tid >> 7;
        int t   = tid & 127;
        int off = grp ? m0 : n0;
        uint32_t* HI = grp ? SB_HI : SA_HI;
        uint32_t* LO = grp ? SB_LO : SA_LO;
        const float* xb = x + (size_t)b*CC*NN + off + t;
        #pragma unroll 8
        for (int c = 0; c < CC; c += 2) {
            float v0 = xb[(size_t)c*NN];
            float v1 = xb[(size_t)(c+1)*NN];
            __nv_bfloat16 h0 = __float2bfloat16_rn(v0);
            __nv_bfloat16 h1 = __float2bfloat16_rn(v1);
            float l0 = v0 - __bfloat162float(h0);
            float l1 = v1 - __bfloat162float(h1);
            __nv_bfloat162 hp; hp.x = h0; hp.y = h1;
            __nv_bfloat162 lp = __floats2bfloat162_rn(l0, l1);
            HI[t*ROW_W + (c>>1)] = *(uint32_t*)&hp;
            LO[t*ROW_W + (c>>1)] = *(uint32_t*)&lp;
        }
    }
    if (tid < 128) sqm[tid] = g_sq[b*NN + m0 + tid];
    __syncthreads();

    int w = tid >> 5, lane = tid & 31;
    int g = lane >> 2, tq = lane & 3;
    int ar = w*16 + g;

    float acc[16][4];
    #pragma unroll
    for (int i = 0; i < 16; i++) { acc[i][0]=acc[i][1]=acc[i][2]=acc[i][3]=0.f; }

    #pragma unroll
    for (int kt = 0; kt < 8; kt++) {
        int kw = kt*8 + tq;
        uint32_t ah[4], al[4];
        ah[0] = SA_HI[ ar     *ROW_W + kw  ];
        ah[1] = SA_HI[(ar+8)  *ROW_W + kw  ];
        ah[2] = SA_HI[ ar     *ROW_W + kw+4];
        ah[3] = SA_HI[(ar+8)  *ROW_W + kw+4];
        al[0] = SA_LO[ ar     *ROW_W + kw  ];
        al[1] = SA_LO[(ar+8)  *ROW_W + kw  ];
        al[2] = SA_LO[ ar     *ROW_W + kw+4];
        al[3] = SA_LO[(ar+8)  *ROW_W + kw+4];
        #pragma unroll
        for (int bt = 0; bt < 16; bt++) {
            int br = bt*8 + g;
            uint32_t bh[2], bl[2];
            bh[0] = SB_HI[br*ROW_W + kw  ];
            bh[1] = SB_HI[br*ROW_W + kw+4];
            bl[0] = SB_LO[br*ROW_W + kw  ];
            bl[1] = SB_LO[br*ROW_W + kw+4];
            mma16816(acc[bt], ah, bh);   // hi*hi
            mma16816(acc[bt], ah, bl);   // hi*lo
            mma16816(acc[bt], al, bh);   // lo*hi
        }
    }

    // fused top-9 (key = sq_m - 2*dot; (d, idx)-lexicographic insertion)
    #pragma unroll
    for (int r = 0; r < 2; r++) {
        int row = n0 + w*16 + g + r*8;
        float bd[KK]; int bi[KK];
        #pragma unroll
        for (int k = 0; k < KK; k++) { bd[k] = 3.4e38f; bi[k] = 0x7fffffff; }
        float wmax = 3.4e38f; int wi = 0x7fffffff; int wpos = 0;

        #pragma unroll
        for (int bt = 0; bt < 16; bt++) {
            #pragma unroll
            for (int q = 0; q < 2; q++) {
                int mloc = bt*8 + tq*2 + q;
                float d = fmaf(-2.f, acc[bt][r*2 + q], sqm[mloc]);
                int   i = b*NN + m0 + mloc;
                if (d < wmax || (d == wmax && i < wi)) {
                    #pragma unroll
                    for (int k = 0; k < KK; k++)
                        if (k == wpos) { bd[k] = d; bi[k] = i; }
                    wmax = bd[0]; wi = bi[0]; wpos = 0;
                    #pragma unroll
                    for (int k = 1; k < KK; k++)
                        if (bd[k] > wmax || (bd[k] == wmax && bi[k] > wi)) {
                            wmax = bd[k]; wi = bi[k]; wpos = k;
                        }
                }
            }
        }
        // quad merge: xor 1 then xor 2 (all lanes converge to the union top-9)
        #pragma unroll
        for (int st = 1; st <= 2; st <<= 1) {
            float od[KK]; int oi[KK];
            #pragma unroll
            for (int k = 0; k < KK; k++) {
                od[k] = __shfl_xor_sync(0xffffffffu, bd[k], st);
                oi[k] = __shfl_xor_sync(0xffffffffu, bi[k], st);
            }
            #pragma unroll
            for (int k2 = 0; k2 < KK; k2++) {
                float d = od[k2]; int i = oi[k2];
                if (d < wmax || (d == wmax && i < wi)) {
                    #pragma unroll
                    for (int k = 0; k < KK; k++)
                        if (k == wpos) { bd[k] = d; bi[k] = i; }
                    wmax = bd[0]; wi = bi[0]; wpos = 0;
                    #pragma unroll
                    for (int k = 1; k < KK; k++)
                        if (bd[k] > wmax || (bd[k] == wmax && bi[k] > wi)) {
                            wmax = bd[k]; wi = bi[k]; wpos = k;
                        }
                }
            }
        }
        if (tq == 0) {
            int pt = b*NN + row;
            #pragma unroll
            for (int k = 0; k < KK; k++) {
                int slot = blockIdx.y*KK + k;
                g_cd[slot*NPT + pt] = bd[k];
                g_ci[slot*NPT + pt] = bi[k];
            }
        }
    }
}

// ---------------- K2c: merge 8 chunk top-9 lists -> final top-9 ----------------
__global__ void __launch_bounds__(128) k_merge()
{
    int pt = blockIdx.x * 128 + threadIdx.x;
    float bd[KK]; int bi[KK];
    #pragma unroll
    for (int k = 0; k < KK; k++) { bd[k] = 3.4e38f; bi[k] = 0x7fffffff; }
    float wmax = 3.4e38f; int wi = 0x7fffffff; int wpos = 0;

    for (int s = 0; s < NCH*KK; s++) {
        float d = g_cd[s*NPT + pt];
        int   i = g_ci[s*NPT + pt];
        if (d < wmax || (d == wmax && i < wi)) {
            #pragma unroll
            for (int k = 0; k < KK; k++)
                if (k == wpos) { bd[k] = d; bi[k] = i; }
            wmax = bd[0]; wi = bi[0]; wpos = 0;
            #pragma unroll
            for (int k = 1; k < KK; k++)
                if (bd[k] > wmax || (bd[k] == wmax && bi[k] > wi)) {
                    wmax = bd[k]; wi = bi[k]; wpos = k;
                }
        }
    }
    #pragma unroll
    for (int k = 0; k < KK; k++) g_idx[pt*KK + k] = bi[k];
}

// ---------------- K3: gather + leaky + (h @ W2) + max_k + BN stats (unchanged) ----------------
__global__ void __launch_bounds__(128, 3) k_edge(
    const float* __restrict__ W2, const float* __restrict__ b2)
{
    __shared__ __align__(16) float h1s[2][KK*CC];
    int j = threadIdx.x;
    int base = blockIdx.x * 16;

    float wcol[CC];
    #pragma unroll
    for (int c = 0; c < CC; c++) wcol[c] = W2[c*CC + j];
    float b2j = b2[j];

    float sumL = 0.f, sqL = 0.f;
    float ga[KK]; float base_h;
    {
        int pt = base;
        base_h = g_u[pt*CC + j] - g_v[pt*CC + j];
        #pragma unroll
        for (int k = 0; k < KK; k++) {
            int nb = g_idx[pt*KK + k];
            ga[k] = g_v[nb*CC + j];
        }
    }

    for (int p = 0; p < 16; p++) {
        int pt = base + p;
        float* hb = h1s[p & 1];
        #pragma unroll
        for (int k = 0; k < KK; k++) {
            float h = base_h + ga[k];
            hb[k*CC + j] = (h >= 0.f) ? h : 0.2f*h;
        }
        __syncthreads();

        if (p < 15) {
            int pn = pt + 1;
            base_h = g_u[pn*CC + j] - g_v[pn*CC + j];
            #pragma unroll
            for (int k = 0; k < KK; k++) {
                int nb = g_idx[pn*KK + k];
                ga[k] = g_v[nb*CC + j];
            }
        }

        float acc[KK];
        #pragma unroll
        for (int k = 0; k < KK; k++) acc[k] = 0.f;
        #pragma unroll
        for (int c = 0; c < CC; c += 4) {
            #pragma unroll
            for (int k = 0; k < KK; k++) {
                float4 h4 = *(const float4*)&hb[k*CC + c];
                float a = acc[k];
                a = fmaf(h4.x, wcol[c  ], a);
                a = fmaf(h4.y, wcol[c+1], a);
                a = fmaf(h4.z, wcol[c+2], a);
                a = fmaf(h4.w, wcol[c+3], a);
                acc[k] = a;
            }
        }
        float m = acc[0];
        #pragma unroll
        for (int k = 1; k < KK; k++) m = fmaxf(m, acc[k]);
        float pre = m + b2j;
        g_pre[pt*CC + j] = pre;
        sumL += pre; sqL += pre*pre;
    }
    atomicAdd(&g_dsum[j], (double)sumL);
    atomicAdd(&g_dsqs[j], (double)sqL);
}

// ---------------- K4: BN scale/shift ----------------
__global__ void k_bn(const float* __restrict__ gamma, const float* __restrict__ beta)
{
    int j = threadIdx.x;
    const double inv = 1.0 / (double)(BB*NN);
    double mean = g_dsum[j] * inv;
    double var  = g_dsqs[j] * inv - mean*mean;
    float sc = gamma[j] * rsqrtf((float)var + 1e-5f);
    g_scale[j] = sc;
    g_shift[j] = beta[j] - (float)mean * sc;
}

// ---------------- K5: transpose + BN apply + residual + ReLU ----------------
__global__ void __launch_bounds__(256) k_apply(
    const float* __restrict__ x, float* __restrict__ out)
{
    __shared__ float tile[32][33];
    int b  = blockIdx.z;
    int c0 = blockIdx.y * 32;
    int n0 = blockIdx.x * 32;
    int t = threadIdx.x;
    int cj = t & 31, i0 = t >> 5;

    for (int i = i0; i < 32; i += 8)
        tile[i][cj] = g_pre[((b*NN) + n0 + i)*CC + c0 + cj];
    __syncthreads();

    int nj = t & 31;
    for (int ci = i0; ci < 32; ci += 8) {
        int c = c0 + ci;
        int o = (b*CC + c)*NN + n0 + nj;
        float v = tile[nj][ci] * g_scale[c] + g_shift[c] + x[o];
        out[o] = v > 0.f ? v : 0.f;
    }
}

// ---------------- launch ----------------
#define GSM_BYTES (4*128*ROW_W*4 + 128*4)   // tiles + sqm

extern "C" void kernel_launch(void* const* d_in, const int* in_sizes, int n_in,
                              void* d_out, int out_size)
{
    const float* x     = (const float*)d_in[0];
    const float* W1    = (const float*)d_in[1];
    const float* b1    = (const float*)d_in[2];
    const float* W2    = (const float*)d_in[3];
    const float* b2    = (const float*)d_in[4];
    const float* gamma = (const float*)d_in[5];
    const float* beta  = (const float*)d_in[6];
    float* out = (float*)d_out;

    cudaFuncSetAttribute(k_gram, cudaFuncAttributeMaxDynamicSharedMemorySize, GSM_BYTES);

    k_init <<<1, 128>>>();
    k_point<<<NPT/16, 128>>>(x, W1, b1);
    k_gram <<<dim3(8, 8, BB), 256, GSM_BYTES>>>(x);
    k_merge<<<NPT/128, 128>>>();
    k_edge <<<NPT/16, 128>>>(W2, b2);
    k_bn   <<<1, 128>>>(gamma, beta);
    k_apply<<<dim3(NN/32, CC/32, BB), 256>>>(x, out);
}

// round 13
// speedup vs baseline: 1.6277x; 1.6277x over previous
#include <cuda_runtime.h>
#include <cuda_bf16.h>
#include <cstdint>

#define BB 16
#define CC 128
#define NN 1024
#define KK 9
#define NCH 8            // topk m-chunks
#define MCH (NN/NCH)     // 128 m per chunk
#define NPT (BB*NN)      // 16384 points
#define ROW_W 68         // smem row stride in 32-bit words (64 data + 4 pad)

// ---- scratch (device globals; no allocation allowed) ----
__device__ float  g_sq[NPT];
__device__ float  g_u[NPT*CC];
__device__ float  g_v[NPT*CC];
__device__ int    g_idx[NPT*KK];
__device__ float  g_pre[NPT*CC];
__device__ float  g_dot[(size_t)NPT*NN];   // 67MB: dot[b][n][m] (symmetric)
__device__ float  g_cd[NCH*KK*NPT];
__device__ int    g_ci[NCH*KK*NPT];
__device__ double g_dsum[CC];
__device__ double g_dsqs[CC];
__device__ float  g_scale[CC];
__device__ float  g_shift[CC];

// warp-level bf16 MMA (PTX ISA 7.0+, compiles on compute_103 -> HMMA)
__device__ __forceinline__ void mma16816(float* c, const uint32_t* a, const uint32_t* b) {
    asm volatile(
        "mma.sync.aligned.m16n8k16.row.col.f32.bf16.bf16.f32 "
        "{%0,%1,%2,%3}, {%4,%5,%6,%7}, {%8,%9}, {%0,%1,%2,%3};"
        : "+f"(c[0]), "+f"(c[1]), "+f"(c[2]), "+f"(c[3])
        : "r"(a[0]), "r"(a[1]), "r"(a[2]), "r"(a[3]), "r"(b[0]), "r"(b[1]));
}

// ---------------- K0 ----------------
__global__ void k_init() {
    int t = threadIdx.x;
    g_dsum[t] = 0.0; g_dsqs[t] = 0.0;
}

// ---------------- K1: per-point sq, u, v ----------------
__global__ void __launch_bounds__(128) k_point(
    const float* __restrict__ x, const float* __restrict__ W1,
    const float* __restrict__ b1)
{
    __shared__ float fs[16*130];
    int t = threadIdx.x;
    int base = blockIdx.x * 16;
    int b = base / NN, n0 = base % NN;
    {
        int p = t & 15, c0 = t >> 4;
        #pragma unroll
        for (int i = 0; i < 16; i++) {
            int c = c0 + i*8;
            fs[p*130 + c] = x[(b*CC + c)*NN + n0 + p];
        }
    }
    __syncthreads();
    if (t < 16) {
        float s = 0.f;
        #pragma unroll 4
        for (int c = 0; c < CC; c++) { float f = fs[t*130+c]; s += f*f; }
        g_sq[base + t] = s;
    }
    int j = t;
    float accU[16], accV[16];
    #pragma unroll
    for (int p = 0; p < 16; p++) { accU[p]=0.f; accV[p]=0.f; }
    for (int c = 0; c < CC; c++) {
        float wa = W1[c*CC + j];
        float wb = W1[(CC+c)*CC + j];
        #pragma unroll
        for (int p = 0; p < 16; p++) {
            float f = fs[p*130 + c];
            accU[p] = fmaf(f, wa, accU[p]);
            accV[p] = fmaf(f, wb, accV[p]);
        }
    }
    float bj = b1[j];
    #pragma unroll
    for (int p = 0; p < 16; p++) {
        g_u[(base+p)*CC + j] = accU[p] + bj;
        g_v[(base+p)*CC + j] = accV[p];
    }
}

// ---------------- K2a: tensor-core gram via mma.sync (3-term double-bf16) ----------------
// Exact round-10 version (verified 460us config).
__global__ void __launch_bounds__(256) k_gram(const float* __restrict__ x)
{
    extern __shared__ __align__(16) uint32_t sm[];
    uint32_t* SA_HI = sm;
    uint32_t* SA_LO = sm + 128*ROW_W;
    uint32_t* SB_HI = sm + 2*128*ROW_W;
    uint32_t* SB_LO = sm + 3*128*ROW_W;

    int tid = threadIdx.x;
    int b  = blockIdx.z;
    int n0 = blockIdx.x * 128, m0 = blockIdx.y * 128;

    {
        int grp = tid >> 7;
        int t   = tid & 127;
        int off = grp ? m0 : n0;
        uint32_t* HI = grp ? SB_HI : SA_HI;
        uint32_t* LO = grp ? SB_LO : SA_LO;
        const float* xb = x + (size_t)b*CC*NN + off + t;
        #pragma unroll 8
        for (int c = 0; c < CC; c += 2) {
            float v0 = xb[(size_t)c*NN];
            float v1 = xb[(size_t)(c+1)*NN];
            __nv_bfloat16 h0 = __float2bfloat16_rn(v0);
            __nv_bfloat16 h1 = __float2bfloat16_rn(v1);
            float l0 = v0 - __bfloat162float(h0);
            float l1 = v1 - __bfloat162float(h1);
            __nv_bfloat162 hp; hp.x = h0; hp.y = h1;
            __nv_bfloat162 lp = __floats2bfloat162_rn(l0, l1);
            HI[t*ROW_W + (c>>1)] = *(uint32_t*)&hp;
            LO[t*ROW_W + (c>>1)] = *(uint32_t*)&lp;
        }
    }
    __syncthreads();

    int w = tid >> 5, lane = tid & 31;
    int g = lane >> 2, tq = lane & 3;
    int ar = w*16 + g;

    float acc[16][4];
    #pragma unroll
    for (int i = 0; i < 16; i++) { acc[i][0]=acc[i][1]=acc[i][2]=acc[i][3]=0.f; }

    #pragma unroll
    for (int kt = 0; kt < 8; kt++) {
        int kw = kt*8 + tq;
        uint32_t ah[4], al[4];
        ah[0] = SA_HI[ ar     *ROW_W + kw  ];
        ah[1] = SA_HI[(ar+8)  *ROW_W + kw  ];
        ah[2] = SA_HI[ ar     *ROW_W + kw+4];
        ah[3] = SA_HI[(ar+8)  *ROW_W + kw+4];
        al[0] = SA_LO[ ar     *ROW_W + kw  ];
        al[1] = SA_LO[(ar+8)  *ROW_W + kw  ];
        al[2] = SA_LO[ ar     *ROW_W + kw+4];
        al[3] = SA_LO[(ar+8)  *ROW_W + kw+4];
        #pragma unroll
        for (int bt = 0; bt < 16; bt++) {
            int br = bt*8 + g;
            uint32_t bh[2], bl[2];
            bh[0] = SB_HI[br*ROW_W + kw  ];
            bh[1] = SB_HI[br*ROW_W + kw+4];
            bl[0] = SB_LO[br*ROW_W + kw  ];
            bl[1] = SB_LO[br*ROW_W + kw+4];
            mma16816(acc[bt], ah, bh);   // hi*hi
            mma16816(acc[bt], ah, bl);   // hi*lo
            mma16816(acc[bt], al, bh);   // lo*hi
        }
    }

    int arow = n0 + w*16 + g;
    #pragma unroll
    for (int bt = 0; bt < 16; bt++) {
        int m = m0 + bt*8 + tq*2;
        float2 v01 = make_float2(acc[bt][0], acc[bt][1]);
        float2 v23 = make_float2(acc[bt][2], acc[bt][3]);
        *(float2*)&g_dot[(size_t)(b*NN + arow    )*NN + m] = v01;
        *(float2*)&g_dot[(size_t)(b*NN + arow + 8)*NN + m] = v23;
    }
}

// ---------------- K2b: chunked top-9 from dot matrix ----------------
// NCH=8 (512 blocks) + unroll 8 -> MLP 8: DRAM-rate scan instead of latency-bound.
__global__ void __launch_bounds__(256) k_topk()
{
    int n  = blockIdx.x * 256 + threadIdx.x;
    int b  = blockIdx.y;
    int ch = blockIdx.z;
    int pt = b*NN + n;
    float sq_n = g_sq[pt];

    float bd[KK]; int bi[KK];
    #pragma unroll
    for (int k = 0; k < KK; k++) { bd[k] = 3.4e38f; bi[k] = 0; }
    float wmax = 3.4e38f; int wpos = 0;

    int mbase = ch*MCH;
    const float* drow = g_dot + (size_t)(b*NN + mbase)*NN + n;
    #pragma unroll 8
    for (int i = 0; i < MCH; i++) {
        int m = mbase + i;
        float dot = drow[(size_t)i*NN];
        float d2v = sq_n + g_sq[b*NN + m] - 2.f*dot;
        if (d2v < wmax) {
            #pragma unroll
            for (int k = 0; k < KK; k++)
                if (k == wpos) { bd[k] = d2v; bi[k] = m; }
            wmax = bd[0]; wpos = 0;
            #pragma unroll
            for (int k = 1; k < KK; k++)
                if (bd[k] > wmax) { wmax = bd[k]; wpos = k; }
        }
    }
    #pragma unroll
    for (int k = 0; k < KK; k++) {
        int slot = ch*KK + k;
        g_cd[slot*NPT + pt] = bd[k];
        g_ci[slot*NPT + pt] = b*NN + bi[k];
    }
}

// ---------------- K2c: merge 8 chunk top-9 lists -> final top-9 ----------------
__global__ void __launch_bounds__(128) k_merge()
{
    int pt = blockIdx.x * 128 + threadIdx.x;
    float bd[KK]; int bi[KK];
    #pragma unroll
    for (int k = 0; k < KK; k++) { bd[k] = 3.4e38f; bi[k] = 0x7fffffff; }
    float wmax = 3.4e38f; int wi = 0x7fffffff; int wpos = 0;

    #pragma unroll 4
    for (int s = 0; s < NCH*KK; s++) {
        float d = g_cd[s*NPT + pt];
        int   i = g_ci[s*NPT + pt];
        if (d < wmax || (d == wmax && i < wi)) {
            #pragma unroll
            for (int k = 0; k < KK; k++)
                if (k == wpos) { bd[k] = d; bi[k] = i; }
            wmax = bd[0]; wi = bi[0]; wpos = 0;
            #pragma unroll
            for (int k = 1; k < KK; k++)
                if (bd[k] > wmax || (bd[k] == wmax && bi[k] > wi)) {
                    wmax = bd[k]; wi = bi[k]; wpos = k;
                }
        }
    }
    #pragma unroll
    for (int k = 0; k < KK; k++) g_idx[pt*KK + k] = bi[k];
}

// ---------------- K3: gather + leaky + (h @ W2) + max_k + BN stats ----------------
__global__ void __launch_bounds__(128, 3) k_edge(
    const float* __restrict__ W2, const float* __restrict__ b2)
{
    __shared__ __align__(16) float h1s[2][KK*CC];
    int j = threadIdx.x;
    int base = blockIdx.x * 16;

    float wcol[CC];
    #pragma unroll
    for (int c = 0; c < CC; c++) wcol[c] = W2[c*CC + j];
    float b2j = b2[j];

    float sumL = 0.f, sqL = 0.f;
    float ga[KK]; float base_h;
    {
        int pt = base;
        base_h = g_u[pt*CC + j] - g_v[pt*CC + j];
        #pragma unroll
        for (int k = 0; k < KK; k++) {
            int nb = g_idx[pt*KK + k];
            ga[k] = g_v[nb*CC + j];
        }
    }

    for (int p = 0; p < 16; p++) {
        int pt = base + p;
        float* hb = h1s[p & 1];
        #pragma unroll
        for (int k = 0; k < KK; k++) {
            float h = base_h + ga[k];
            hb[k*CC + j] = (h >= 0.f) ? h : 0.2f*h;
        }
        __syncthreads();

        if (p < 15) {
            int pn = pt + 1;
            base_h = g_u[pn*CC + j] - g_v[pn*CC + j];
            #pragma unroll
            for (int k = 0; k < KK; k++) {
                int nb = g_idx[pn*KK + k];
                ga[k] = g_v[nb*CC + j];
            }
        }

        float acc[KK];
        #pragma unroll
        for (int k = 0; k < KK; k++) acc[k] = 0.f;
        #pragma unroll
        for (int c = 0; c < CC; c += 4) {
            #pragma unroll
            for (int k = 0; k < KK; k++) {
                float4 h4 = *(const float4*)&hb[k*CC + c];
                float a = acc[k];
                a = fmaf(h4.x, wcol[c  ], a);
                a = fmaf(h4.y, wcol[c+1], a);
                a = fmaf(h4.z, wcol[c+2], a);
                a = fmaf(h4.w, wcol[c+3], a);
                acc[k] = a;
            }
        }
        float m = acc[0];
        #pragma unroll
        for (int k = 1; k < KK; k++) m = fmaxf(m, acc[k]);
        float pre = m + b2j;
        g_pre[pt*CC + j] = pre;
        sumL += pre; sqL += pre*pre;
    }
    atomicAdd(&g_dsum[j], (double)sumL);
    atomicAdd(&g_dsqs[j], (double)sqL);
}

// ---------------- K4: BN scale/shift ----------------
__global__ void k_bn(const float* __restrict__ gamma, const float* __restrict__ beta)
{
    int j = threadIdx.x;
    const double inv = 1.0 / (double)(BB*NN);
    double mean = g_dsum[j] * inv;
    double var  = g_dsqs[j] * inv - mean*mean;
    float sc = gamma[j] * rsqrtf((float)var + 1e-5f);
    g_scale[j] = sc;
    g_shift[j] = beta[j] - (float)mean * sc;
}

// ---------------- K5: transpose + BN apply + residual + ReLU ----------------
__global__ void __launch_bounds__(256) k_apply(
    const float* __restrict__ x, float* __restrict__ out)
{
    __shared__ float tile[32][33];
    int b  = blockIdx.z;
    int c0 = blockIdx.y * 32;
    int n0 = blockIdx.x * 32;
    int t = threadIdx.x;
    int cj = t & 31, i0 = t >> 5;

    for (int i = i0; i < 32; i += 8)
        tile[i][cj] = g_pre[((b*NN) + n0 + i)*CC + c0 + cj];
    __syncthreads();

    int nj = t & 31;
    for (int ci = i0; ci < 32; ci += 8) {
        int c = c0 + ci;
        int o = (b*CC + c)*NN + n0 + nj;
        float v = tile[nj][ci] * g_scale[c] + g_shift[c] + x[o];
        out[o] = v > 0.f ? v : 0.f;
    }
}

// ---------------- launch ----------------
#define GSM_BYTES (4*128*ROW_W*4)   // 139264

extern "C" void kernel_launch(void* const* d_in, const int* in_sizes, int n_in,
                              void* d_out, int out_size)
{
    const float* x     = (const float*)d_in[0];
    const float* W1    = (const float*)d_in[1];
    const float* b1    = (const float*)d_in[2];
    const float* W2    = (const float*)d_in[3];
    const float* b2    = (const float*)d_in[4];
    const float* gamma = (const float*)d_in[5];
    const float* beta  = (const float*)d_in[6];
    float* out = (float*)d_out;

    cudaFuncSetAttribute(k_gram, cudaFuncAttributeMaxDynamicSharedMemorySize, GSM_BYTES);

    k_init <<<1, 128>>>();
    k_point<<<NPT/16, 128>>>(x, W1, b1);
    k_gram <<<dim3(8, 8, BB), 256, GSM_BYTES>>>(x);
    k_topk <<<dim3(NN/256, BB, NCH), 256>>>();
    k_merge<<<NPT/128, 128>>>();
    k_edge <<<NPT/16, 128>>>(W2, b2);
    k_bn   <<<1, 128>>>(gamma, beta);
    k_apply<<<dim3(NN/32, CC/32, BB), 256>>>(x, out);
}

// round 14
// speedup vs baseline: 2.1040x; 1.2926x over previous
#include <cuda_runtime.h>
#include <cuda_bf16.h>
#include <cstdint>

#define BB 16
#define CC 128
#define NN 1024
#define KK 9
#define NCH 8            // topk m-chunks
#define MCH (NN/NCH)     // 128 m per chunk
#define NPT (BB*NN)      // 16384 points
#define ROW_W 68         // smem row stride in 32-bit words (64 data + 4 pad)

// ---- scratch (device globals; no allocation allowed) ----
__device__ float  g_sq[NPT];
__device__ float  g_u[NPT*CC];
__device__ float  g_v[NPT*CC];
__device__ int    g_idx[NPT*KK];
__device__ float  g_pre[NPT*CC];
__device__ float  g_dot[(size_t)NPT*NN];   // 67MB: dot[b][n][m] (symmetric)
__device__ float  g_cd[NCH*KK*NPT];
__device__ int    g_ci[NCH*KK*NPT];
__device__ double g_dsum[CC];
__device__ double g_dsqs[CC];
__device__ float  g_scale[CC];
__device__ float  g_shift[CC];

// warp-level bf16 MMA (PTX ISA 7.0+, compiles on compute_103 -> HMMA)
__device__ __forceinline__ void mma16816(float* c, const uint32_t* a, const uint32_t* b) {
    asm volatile(
        "mma.sync.aligned.m16n8k16.row.col.f32.bf16.bf16.f32 "
        "{%0,%1,%2,%3}, {%4,%5,%6,%7}, {%8,%9}, {%0,%1,%2,%3};"
        : "+f"(c[0]), "+f"(c[1]), "+f"(c[2]), "+f"(c[3])
        : "r"(a[0]), "r"(a[1]), "r"(a[2]), "r"(a[3]), "r"(b[0]), "r"(b[1]));
}

__device__ __forceinline__ uint32_t pack_bf16x2(float f0, float f1) {
    __nv_bfloat162 t = __floats2bfloat162_rn(f0, f1);
    return *reinterpret_cast<uint32_t*>(&t);
}

// ---------------- K0 ----------------
__global__ void k_init() {
    int t = threadIdx.x;
    g_dsum[t] = 0.0; g_dsqs[t] = 0.0;
}

// ---------------- K1: per-point sq, u, v ----------------
__global__ void __launch_bounds__(128) k_point(
    const float* __restrict__ x, const float* __restrict__ W1,
    const float* __restrict__ b1)
{
    __shared__ float fs[16*130];
    int t = threadIdx.x;
    int base = blockIdx.x * 16;
    int b = base / NN, n0 = base % NN;
    {
        int p = t & 15, c0 = t >> 4;
        #pragma unroll
        for (int i = 0; i < 16; i++) {
            int c = c0 + i*8;
            fs[p*130 + c] = x[(b*CC + c)*NN + n0 + p];
        }
    }
    __syncthreads();
    if (t < 16) {
        float s = 0.f;
        #pragma unroll 4
        for (int c = 0; c < CC; c++) { float f = fs[t*130+c]; s += f*f; }
        g_sq[base + t] = s;
    }
    int j = t;
    float accU[16], accV[16];
    #pragma unroll
    for (int p = 0; p < 16; p++) { accU[p]=0.f; accV[p]=0.f; }
    for (int c = 0; c < CC; c++) {
        float wa = W1[c*CC + j];
        float wb = W1[(CC+c)*CC + j];
        #pragma unroll
        for (int p = 0; p < 16; p++) {
            float f = fs[p*130 + c];
            accU[p] = fmaf(f, wa, accU[p]);
            accV[p] = fmaf(f, wb, accV[p]);
        }
    }
    float bj = b1[j];
    #pragma unroll
    for (int p = 0; p < 16; p++) {
        g_u[(base+p)*CC + j] = accU[p] + bj;
        g_v[(base+p)*CC + j] = accV[p];
    }
}

// ---------------- K2a: tensor-core gram via mma.sync (3-term double-bf16) ----------------
__global__ void __launch_bounds__(256) k_gram(const float* __restrict__ x)
{
    extern __shared__ __align__(16) uint32_t sm[];
    uint32_t* SA_HI = sm;
    uint32_t* SA_LO = sm + 128*ROW_W;
    uint32_t* SB_HI = sm + 2*128*ROW_W;
    uint32_t* SB_LO = sm + 3*128*ROW_W;

    int tid = threadIdx.x;
    int b  = blockIdx.z;
    int n0 = blockIdx.x * 128, m0 = blockIdx.y * 128;

    {
        int grp = tid >> 7;
        int t   = tid & 127;
        int off = grp ? m0 : n0;
        uint32_t* HI = grp ? SB_HI : SA_HI;
        uint32_t* LO = grp ? SB_LO : SA_LO;
        const float* xb = x + (size_t)b*CC*NN + off + t;
        #pragma unroll 8
        for (int c = 0; c < CC; c += 2) {
            float v0 = xb[(size_t)c*NN];
            float v1 = xb[(size_t)(c+1)*NN];
            __nv_bfloat16 h0 = __float2bfloat16_rn(v0);
            __nv_bfloat16 h1 = __float2bfloat16_rn(v1);
            float l0 = v0 - __bfloat162float(h0);
            float l1 = v1 - __bfloat162float(h1);
            __nv_bfloat162 hp; hp.x = h0; hp.y = h1;
            __nv_bfloat162 lp = __floats2bfloat162_rn(l0, l1);
            HI[t*ROW_W + (c>>1)] = *(uint32_t*)&hp;
            LO[t*ROW_W + (c>>1)] = *(uint32_t*)&lp;
        }
    }
    __syncthreads();

    int w = tid >> 5, lane = tid & 31;
    int g = lane >> 2, tq = lane & 3;
    int ar = w*16 + g;

    float acc[16][4];
    #pragma unroll
    for (int i = 0; i < 16; i++) { acc[i][0]=acc[i][1]=acc[i][2]=acc[i][3]=0.f; }

    #pragma unroll
    for (int kt = 0; kt < 8; kt++) {
        int kw = kt*8 + tq;
        uint32_t ah[4], al[4];
        ah[0] = SA_HI[ ar     *ROW_W + kw  ];
        ah[1] = SA_HI[(ar+8)  *ROW_W + kw  ];
        ah[2] = SA_HI[ ar     *ROW_W + kw+4];
        ah[3] = SA_HI[(ar+8)  *ROW_W + kw+4];
        al[0] = SA_LO[ ar     *ROW_W + kw  ];
        al[1] = SA_LO[(ar+8)  *ROW_W + kw  ];
        al[2] = SA_LO[ ar     *ROW_W + kw+4];
        al[3] = SA_LO[(ar+8)  *ROW_W + kw+4];
        #pragma unroll
        for (int bt = 0; bt < 16; bt++) {
            int br = bt*8 + g;
            uint32_t bh[2], bl[2];
            bh[0] = SB_HI[br*ROW_W + kw  ];
            bh[1] = SB_HI[br*ROW_W + kw+4];
            bl[0] = SB_LO[br*ROW_W + kw  ];
            bl[1] = SB_LO[br*ROW_W + kw+4];
            mma16816(acc[bt], ah, bh);   // hi*hi
            mma16816(acc[bt], ah, bl);   // hi*lo
            mma16816(acc[bt], al, bh);   // lo*hi
        }
    }

    int arow = n0 + w*16 + g;
    #pragma unroll
    for (int bt = 0; bt < 16; bt++) {
        int m = m0 + bt*8 + tq*2;
        float2 v01 = make_float2(acc[bt][0], acc[bt][1]);
        float2 v23 = make_float2(acc[bt][2], acc[bt][3]);
        *(float2*)&g_dot[(size_t)(b*NN + arow    )*NN + m] = v01;
        *(float2*)&g_dot[(size_t)(b*NN + arow + 8)*NN + m] = v23;
    }
}

// ---------------- K2b: chunked top-9 from dot matrix ----------------
__global__ void __launch_bounds__(256) k_topk()
{
    int n  = blockIdx.x * 256 + threadIdx.x;
    int b  = blockIdx.y;
    int ch = blockIdx.z;
    int pt = b*NN + n;
    float sq_n = g_sq[pt];

    float bd[KK]; int bi[KK];
    #pragma unroll
    for (int k = 0; k < KK; k++) { bd[k] = 3.4e38f; bi[k] = 0; }
    float wmax = 3.4e38f; int wpos = 0;

    int mbase = ch*MCH;
    const float* drow = g_dot + (size_t)(b*NN + mbase)*NN + n;
    #pragma unroll 8
    for (int i = 0; i < MCH; i++) {
        int m = mbase + i;
        float dot = drow[(size_t)i*NN];
        float d2v = sq_n + g_sq[b*NN + m] - 2.f*dot;
        if (d2v < wmax) {
            #pragma unroll
            for (int k = 0; k < KK; k++)
                if (k == wpos) { bd[k] = d2v; bi[k] = m; }
            wmax = bd[0]; wpos = 0;
            #pragma unroll
            for (int k = 1; k < KK; k++)
                if (bd[k] > wmax) { wmax = bd[k]; wpos = k; }
        }
    }
    #pragma unroll
    for (int k = 0; k < KK; k++) {
        int slot = ch*KK + k;
        g_cd[slot*NPT + pt] = bd[k];
        g_ci[slot*NPT + pt] = b*NN + bi[k];
    }
}

// ---------------- K2c: merge 8 chunk top-9 lists -> final top-9 ----------------
__global__ void __launch_bounds__(128) k_merge()
{
    int pt = blockIdx.x * 128 + threadIdx.x;
    float bd[KK]; int bi[KK];
    #pragma unroll
    for (int k = 0; k < KK; k++) { bd[k] = 3.4e38f; bi[k] = 0x7fffffff; }
    float wmax = 3.4e38f; int wi = 0x7fffffff; int wpos = 0;

    #pragma unroll 4
    for (int s = 0; s < NCH*KK; s++) {
        float d = g_cd[s*NPT + pt];
        int   i = g_ci[s*NPT + pt];
        if (d < wmax || (d == wmax && i < wi)) {
            #pragma unroll
            for (int k = 0; k < KK; k++)
                if (k == wpos) { bd[k] = d; bi[k] = i; }
            wmax = bd[0]; wi = bi[0]; wpos = 0;
            #pragma unroll
            for (int k = 1; k < KK; k++)
                if (bd[k] > wmax || (bd[k] == wmax && bi[k] > wi)) {
                    wmax = bd[k]; wi = bi[k]; wpos = k;
                }
        }
    }
    #pragma unroll
    for (int k = 0; k < KK; k++) g_idx[pt*KK + k] = bi[k];
}

// ---------------- K3: edge MLP layer-2 on tensor cores ----------------
// Block: 16 points, 256 thr (8 warps). H = leaky(u - v + v[nb]) staged as
// 144 rows (p*9+kk) x 128c bf16 hi/lo; W2^T staged as col-major B (c'-rows).
// Warp w owns output cols [16w, 16w+16): per kk, 8 k-steps x 2 n-tiles x 3
// terms (hh+hl+lh), then running max over kk in regs; bias after max.
#define ESA_HI 0
#define ESA_LO (144*ROW_W)
#define ESB_HI (2*144*ROW_W)
#define ESB_LO (2*144*ROW_W + 128*ROW_W)
#define ESM_WORDS (2*144*ROW_W + 2*128*ROW_W)

__global__ void __launch_bounds__(256) k_edge(
    const float* __restrict__ W2, const float* __restrict__ b2)
{
    extern __shared__ __align__(16) uint32_t esm[];
    int tid = threadIdx.x;
    int base = blockIdx.x * 16;
    int w = tid >> 5, lane = tid & 31;

    // stage W2^T: row c' holds W2[:, c'] (col-major B operand), hi/lo split
    for (int idx = tid; idx < 128*64; idx += 256) {
        int cp = idx & 127;          // c' (output channel)
        int cw = idx >> 7;           // word: input channels 2cw, 2cw+1
        float w0 = W2[(2*cw)*CC + cp];      // coalesced over cp
        float w1 = W2[(2*cw+1)*CC + cp];
        __nv_bfloat16 h0 = __float2bfloat16_rn(w0);
        __nv_bfloat16 h1 = __float2bfloat16_rn(w1);
        esm[ESB_HI + cp*ROW_W + cw] = pack_bf16x2(w0, w1);
        esm[ESB_LO + cp*ROW_W + cw] =
            pack_bf16x2(w0 - __bfloat162float(h0), w1 - __bfloat162float(h1));
    }

    // stage H rows: warp w builds rows [18w, 18w+18)
    #pragma unroll 2
    for (int ri = 0; ri < 18; ri++) {
        int r = w*18 + ri;
        int p = r / 9, kk = r - p*9;
        int pt = base + p;
        float4 u4 = *(const float4*)&g_u[pt*CC + lane*4];
        float4 v4 = *(const float4*)&g_v[pt*CC + lane*4];
        int nb = g_idx[pt*KK + kk];                      // uniform
        float4 gv = *(const float4*)&g_v[nb*CC + lane*4];
        float h0 = u4.x - v4.x + gv.x; h0 = h0 >= 0.f ? h0 : 0.2f*h0;
        float h1 = u4.y - v4.y + gv.y; h1 = h1 >= 0.f ? h1 : 0.2f*h1;
        float h2 = u4.z - v4.z + gv.z; h2 = h2 >= 0.f ? h2 : 0.2f*h2;
        float h3 = u4.w - v4.w + gv.w; h3 = h3 >= 0.f ? h3 : 0.2f*h3;
        __nv_bfloat16 t0 = __float2bfloat16_rn(h0);
        __nv_bfloat16 t1 = __float2bfloat16_rn(h1);
        __nv_bfloat16 t2 = __float2bfloat16_rn(h2);
        __nv_bfloat16 t3 = __float2bfloat16_rn(h3);
        *(uint2*)&esm[ESA_HI + r*ROW_W + lane*2] =
            make_uint2(pack_bf16x2(h0, h1), pack_bf16x2(h2, h3));
        *(uint2*)&esm[ESA_LO + r*ROW_W + lane*2] =
            make_uint2(pack_bf16x2(h0 - __bfloat162float(t0), h1 - __bfloat162float(t1)),
                       pack_bf16x2(h2 - __bfloat162float(t2), h3 - __bfloat162float(t3)));
    }
    __syncthreads();

    int g = lane >> 2, tq = lane & 3;
    int nbase = w*16;

    float mx[2][4];
    #pragma unroll
    for (int nt = 0; nt < 2; nt++)
        #pragma unroll
        for (int i = 0; i < 4; i++) mx[nt][i] = -3.4e38f;

    #pragma unroll
    for (int kk = 0; kk < KK; kk++) {
        float acc[2][4];
        #pragma unroll
        for (int nt = 0; nt < 2; nt++)
            #pragma unroll
            for (int i = 0; i < 4; i++) acc[nt][i] = 0.f;
        int r0 = g*9 + kk, r1 = (g+8)*9 + kk;
        #pragma unroll
        for (int kt = 0; kt < 8; kt++) {
            int kw = kt*8 + tq;
            uint32_t ah[4], al[4];
            ah[0] = esm[ESA_HI + r0*ROW_W + kw  ];
            ah[1] = esm[ESA_HI + r1*ROW_W + kw  ];
            ah[2] = esm[ESA_HI + r0*ROW_W + kw+4];
            ah[3] = esm[ESA_HI + r1*ROW_W + kw+4];
            al[0] = esm[ESA_LO + r0*ROW_W + kw  ];
            al[1] = esm[ESA_LO + r1*ROW_W + kw  ];
            al[2] = esm[ESA_LO + r0*ROW_W + kw+4];
            al[3] = esm[ESA_LO + r1*ROW_W + kw+4];
            #pragma unroll
            for (int nt = 0; nt < 2; nt++) {
                int br = nbase + nt*8 + g;
                uint32_t bh[2], bl[2];
                bh[0] = esm[ESB_HI + br*ROW_W + kw  ];
                bh[1] = esm[ESB_HI + br*ROW_W + kw+4];
                bl[0] = esm[ESB_LO + br*ROW_W + kw  ];
                bl[1] = esm[ESB_LO + br*ROW_W + kw+4];
                mma16816(acc[nt], ah, bh);
                mma16816(acc[nt], ah, bl);
                mma16816(acc[nt], al, bh);
            }
        }
        #pragma unroll
        for (int nt = 0; nt < 2; nt++)
            #pragma unroll
            for (int i = 0; i < 4; i++) mx[nt][i] = fmaxf(mx[nt][i], acc[nt][i]);
    }

    // bias after max + write g_pre (rows g, g+8; cols nbase+nt*8+tq*2)
    int p0 = base + g, p1 = base + g + 8;
    #pragma unroll
    for (int nt = 0; nt < 2; nt++) {
        int c = nbase + nt*8 + tq*2;
        float bb0 = b2[c], bb1 = b2[c+1];
        *(float2*)&g_pre[p0*CC + c] = make_float2(mx[nt][0] + bb0, mx[nt][1] + bb1);
        *(float2*)&g_pre[p1*CC + c] = make_float2(mx[nt][2] + bb0, mx[nt][3] + bb1);
    }
}

// ---------------- K3b: BN statistics (coalesced scan of g_pre) ----------------
__global__ void __launch_bounds__(256) k_stats()
{
    __shared__ float ss[128], qs[128];
    int t = threadIdx.x, c = t & 127, half = t >> 7;
    int p0 = blockIdx.x * 128 + half*64;
    float s = 0.f, q = 0.f;
    #pragma unroll 4
    for (int p = 0; p < 64; p++) {
        float v = g_pre[(p0 + p)*CC + c];
        s += v; q += v*v;
    }
    if (half) { ss[c] = s; qs[c] = q; }
    __syncthreads();
    if (!half) {
        s += ss[c]; q += qs[c];
        atomicAdd(&g_dsum[c], (double)s);
        atomicAdd(&g_dsqs[c], (double)q);
    }
}

// ---------------- K4: BN scale/shift ----------------
__global__ void k_bn(const float* __restrict__ gamma, const float* __restrict__ beta)
{
    int j = threadIdx.x;
    const double inv = 1.0 / (double)(BB*NN);
    double mean = g_dsum[j] * inv;
    double var  = g_dsqs[j] * inv - mean*mean;
    float sc = gamma[j] * rsqrtf((float)var + 1e-5f);
    g_scale[j] = sc;
    g_shift[j] = beta[j] - (float)mean * sc;
}

// ---------------- K5: transpose + BN apply + residual + ReLU ----------------
__global__ void __launch_bounds__(256) k_apply(
    const float* __restrict__ x, float* __restrict__ out)
{
    __shared__ float tile[32][33];
    int b  = blockIdx.z;
    int c0 = blockIdx.y * 32;
    int n0 = blockIdx.x * 32;
    int t = threadIdx.x;
    int cj = t & 31, i0 = t >> 5;

    for (int i = i0; i < 32; i += 8)
        tile[i][cj] = g_pre[((b*NN) + n0 + i)*CC + c0 + cj];
    __syncthreads();

    int nj = t & 31;
    for (int ci = i0; ci < 32; ci += 8) {
        int c = c0 + ci;
        int o = (b*CC + c)*NN + n0 + nj;
        float v = tile[nj][ci] * g_scale[c] + g_shift[c] + x[o];
        out[o] = v > 0.f ? v : 0.f;
    }
}

// ---------------- launch ----------------
#define GSM_BYTES (4*128*ROW_W*4)       // k_gram smem
#define ESM_BYTES (ESM_WORDS*4)         // k_edge smem (147968)

extern "C" void kernel_launch(void* const* d_in, const int* in_sizes, int n_in,
                              void* d_out, int out_size)
{
    const float* x     = (const float*)d_in[0];
    const float* W1    = (const float*)d_in[1];
    const float* b1    = (const float*)d_in[2];
    const float* W2    = (const float*)d_in[3];
    const float* b2    = (const float*)d_in[4];
    const float* gamma = (const float*)d_in[5];
    const float* beta  = (const float*)d_in[6];
    float* out = (float*)d_out;

    cudaFuncSetAttribute(k_gram, cudaFuncAttributeMaxDynamicSharedMemorySize, GSM_BYTES);
    cudaFuncSetAttribute(k_edge, cudaFuncAttributeMaxDynamicSharedMemorySize, ESM_BYTES);

    k_init <<<1, 128>>>();
    k_point<<<NPT/16, 128>>>(x, W1, b1);
    k_gram <<<dim3(8, 8, BB), 256, GSM_BYTES>>>(x);
    k_topk <<<dim3(NN/256, BB, NCH), 256>>>();
    k_merge<<<NPT/128, 128>>>();
    k_edge <<<NPT/16, 256, ESM_BYTES>>>(W2, b2);
    k_stats<<<NPT/128, 256>>>();
    k_bn   <<<1, 128>>>(gamma, beta);
    k_apply<<<dim3(NN/32, CC/32, BB), 256>>>(x, out);
}

// round 15
// speedup vs baseline: 2.2796x; 1.0834x over previous
#include <cuda_runtime.h>
#include <cuda_bf16.h>
#include <cstdint>

#define BB 16
#define CC 128
#define NN 1024
#define KK 9
#define NCH 8            // topk m-chunks
#define MCH (NN/NCH)     // 128 m per chunk
#define NPT (BB*NN)      // 16384 points
#define ROW_W 68         // smem row stride in 32-bit words (64 data + 4 pad)

// ---- scratch (device globals; no allocation allowed) ----
__device__ float  g_sq[NPT];
__device__ float  g_u[NPT*CC];
__device__ float  g_v[NPT*CC];
__device__ int    g_idx[NPT*KK];
__device__ float  g_pre[NPT*CC];
__device__ float  g_dot[(size_t)NPT*NN];   // 67MB: key[b][n][m] = sq_m - 2*dot
__device__ float  g_cd[NCH*KK*NPT];
__device__ int    g_ci[NCH*KK*NPT];
__device__ double g_dsum[CC];
__device__ double g_dsqs[CC];
__device__ float  g_scale[CC];
__device__ float  g_shift[CC];

// warp-level bf16 MMA (PTX ISA 7.0+, compiles on compute_103 -> HMMA)
__device__ __forceinline__ void mma16816(float* c, const uint32_t* a, const uint32_t* b) {
    asm volatile(
        "mma.sync.aligned.m16n8k16.row.col.f32.bf16.bf16.f32 "
        "{%0,%1,%2,%3}, {%4,%5,%6,%7}, {%8,%9}, {%0,%1,%2,%3};"
        : "+f"(c[0]), "+f"(c[1]), "+f"(c[2]), "+f"(c[3])
        : "r"(a[0]), "r"(a[1]), "r"(a[2]), "r"(a[3]), "r"(b[0]), "r"(b[1]));
}

__device__ __forceinline__ uint32_t pack_bf16x2(float f0, float f1) {
    __nv_bfloat162 t = __floats2bfloat162_rn(f0, f1);
    return *reinterpret_cast<uint32_t*>(&t);
}

// ---------------- K0 ----------------
__global__ void k_init() {
    int t = threadIdx.x;
    g_dsum[t] = 0.0; g_dsqs[t] = 0.0;
}

// ---------------- K1: per-point sq, u, v ----------------
__global__ void __launch_bounds__(128) k_point(
    const float* __restrict__ x, const float* __restrict__ W1,
    const float* __restrict__ b1)
{
    __shared__ float fs[16*130];
    int t = threadIdx.x;
    int base = blockIdx.x * 16;
    int b = base / NN, n0 = base % NN;
    {
        int p = t & 15, c0 = t >> 4;
        #pragma unroll
        for (int i = 0; i < 16; i++) {
            int c = c0 + i*8;
            fs[p*130 + c] = x[(b*CC + c)*NN + n0 + p];
        }
    }
    __syncthreads();
    if (t < 16) {
        float s = 0.f;
        #pragma unroll 4
        for (int c = 0; c < CC; c++) { float f = fs[t*130+c]; s += f*f; }
        g_sq[base + t] = s;
    }
    int j = t;
    float accU[16], accV[16];
    #pragma unroll
    for (int p = 0; p < 16; p++) { accU[p]=0.f; accV[p]=0.f; }
    for (int c = 0; c < CC; c++) {
        float wa = W1[c*CC + j];
        float wb = W1[(CC+c)*CC + j];
        #pragma unroll
        for (int p = 0; p < 16; p++) {
            float f = fs[p*130 + c];
            accU[p] = fmaf(f, wa, accU[p]);
            accV[p] = fmaf(f, wb, accV[p]);
        }
    }
    float bj = b1[j];
    #pragma unroll
    for (int p = 0; p < 16; p++) {
        g_u[(base+p)*CC + j] = accU[p] + bj;
        g_v[(base+p)*CC + j] = accV[p];
    }
}

// ---------------- K2a: tensor gram via mma.sync; epilogue stores key = sq_m - 2*dot ----------------
__global__ void __launch_bounds__(256) k_gram(const float* __restrict__ x)
{
    extern __shared__ __align__(16) uint32_t sm[];
    uint32_t* SA_HI = sm;
    uint32_t* SA_LO = sm + 128*ROW_W;
    uint32_t* SB_HI = sm + 2*128*ROW_W;
    uint32_t* SB_LO = sm + 3*128*ROW_W;
    float*    sqm   = (float*)(sm + 4*128*ROW_W);   // 128 floats

    int tid = threadIdx.x;
    int b  = blockIdx.z;
    int n0 = blockIdx.x * 128, m0 = blockIdx.y * 128;

    {
        int grp = tid >> 7;
        int t   = tid & 127;
        int off = grp ? m0 : n0;
        uint32_t* HI = grp ? SB_HI : SA_HI;
        uint32_t* LO = grp ? SB_LO : SA_LO;
        const float* xb = x + (size_t)b*CC*NN + off + t;
        #pragma unroll 8
        for (int c = 0; c < CC; c += 2) {
            float v0 = xb[(size_t)c*NN];
            float v1 = xb[(size_t)(c+1)*NN];
            __nv_bfloat16 h0 = __float2bfloat16_rn(v0);
            __nv_bfloat16 h1 = __float2bfloat16_rn(v1);
            float l0 = v0 - __bfloat162float(h0);
            float l1 = v1 - __bfloat162float(h1);
            __nv_bfloat162 hp; hp.x = h0; hp.y = h1;
            __nv_bfloat162 lp = __floats2bfloat162_rn(l0, l1);
            HI[t*ROW_W + (c>>1)] = *(uint32_t*)&hp;
            LO[t*ROW_W + (c>>1)] = *(uint32_t*)&lp;
        }
    }
    if (tid < 128) sqm[tid] = g_sq[b*NN + m0 + tid];
    __syncthreads();

    int w = tid >> 5, lane = tid & 31;
    int g = lane >> 2, tq = lane & 3;
    int ar = w*16 + g;

    float acc[16][4];
    #pragma unroll
    for (int i = 0; i < 16; i++) { acc[i][0]=acc[i][1]=acc[i][2]=acc[i][3]=0.f; }

    #pragma unroll
    for (int kt = 0; kt < 8; kt++) {
        int kw = kt*8 + tq;
        uint32_t ah[4], al[4];
        ah[0] = SA_HI[ ar     *ROW_W + kw  ];
        ah[1] = SA_HI[(ar+8)  *ROW_W + kw  ];
        ah[2] = SA_HI[ ar     *ROW_W + kw+4];
        ah[3] = SA_HI[(ar+8)  *ROW_W + kw+4];
        al[0] = SA_LO[ ar     *ROW_W + kw  ];
        al[1] = SA_LO[(ar+8)  *ROW_W + kw  ];
        al[2] = SA_LO[ ar     *ROW_W + kw+4];
        al[3] = SA_LO[(ar+8)  *ROW_W + kw+4];
        #pragma unroll
        for (int bt = 0; bt < 16; bt++) {
            int br = bt*8 + g;
            uint32_t bh[2], bl[2];
            bh[0] = SB_HI[br*ROW_W + kw  ];
            bh[1] = SB_HI[br*ROW_W + kw+4];
            bl[0] = SB_LO[br*ROW_W + kw  ];
            bl[1] = SB_LO[br*ROW_W + kw+4];
            mma16816(acc[bt], ah, bh);   // hi*hi
            mma16816(acc[bt], ah, bl);   // hi*lo
            mma16816(acc[bt], al, bh);   // lo*hi
        }
    }

    int arow = n0 + w*16 + g;
    #pragma unroll
    for (int bt = 0; bt < 16; bt++) {
        int mloc = bt*8 + tq*2;
        int m = m0 + mloc;
        float s0 = sqm[mloc], s1 = sqm[mloc+1];
        float2 v01 = make_float2(fmaf(-2.f, acc[bt][0], s0), fmaf(-2.f, acc[bt][1], s1));
        float2 v23 = make_float2(fmaf(-2.f, acc[bt][2], s0), fmaf(-2.f, acc[bt][3], s1));
        *(float2*)&g_dot[(size_t)(b*NN + arow    )*NN + m] = v01;
        *(float2*)&g_dot[(size_t)(b*NN + arow + 8)*NN + m] = v23;
    }
}

// ---------------- K2b: chunked top-9, contiguous float4 row scan of keys ----------------
__global__ void __launch_bounds__(256) k_topk()
{
    int n  = blockIdx.x * 256 + threadIdx.x;
    int b  = blockIdx.y;
    int ch = blockIdx.z;
    int pt = b*NN + n;

    float bd[KK]; int bi[KK];
    #pragma unroll
    for (int k = 0; k < KK; k++) { bd[k] = 3.4e38f; bi[k] = 0; }
    float wmax = 3.4e38f; int wpos = 0;

    int mbase = ch*MCH;
    const float4* row = (const float4*)(g_dot + (size_t)pt*NN + mbase);
    #pragma unroll 8
    for (int i = 0; i < MCH/4; i++) {
        float4 v4 = row[i];
        float vv[4] = {v4.x, v4.y, v4.z, v4.w};
        #pragma unroll
        for (int q = 0; q < 4; q++) {
            float d2v = vv[q];
            int m = mbase + i*4 + q;
            if (d2v < wmax) {
                #pragma unroll
                for (int k = 0; k < KK; k++)
                    if (k == wpos) { bd[k] = d2v; bi[k] = m; }
                wmax = bd[0]; wpos = 0;
                #pragma unroll
                for (int k = 1; k < KK; k++)
                    if (bd[k] > wmax) { wmax = bd[k]; wpos = k; }
            }
        }
    }
    #pragma unroll
    for (int k = 0; k < KK; k++) {
        int slot = ch*KK + k;
        g_cd[slot*NPT + pt] = bd[k];
        g_ci[slot*NPT + pt] = b*NN + bi[k];
    }
}

// ---------------- K2c: merge 72 slots -> top-9; 4 threads/point + shfl merge ----------------
__global__ void __launch_bounds__(256) k_merge()
{
    int tid = threadIdx.x;
    int q   = tid & 3;
    int pt  = blockIdx.x * 64 + (tid >> 2);

    float bd[KK]; int bi[KK];
    #pragma unroll
    for (int k = 0; k < KK; k++) { bd[k] = 3.4e38f; bi[k] = 0x7fffffff; }
    float wmax = 3.4e38f; int wi = 0x7fffffff; int wpos = 0;

    #pragma unroll 2
    for (int s = q; s < NCH*KK; s += 4) {   // 18 slots each
        float d = g_cd[s*NPT + pt];
        int   i = g_ci[s*NPT + pt];
        if (d < wmax || (d == wmax && i < wi)) {
            #pragma unroll
            for (int k = 0; k < KK; k++)
                if (k == wpos) { bd[k] = d; bi[k] = i; }
            wmax = bd[0]; wi = bi[0]; wpos = 0;
            #pragma unroll
            for (int k = 1; k < KK; k++)
                if (bd[k] > wmax || (bd[k] == wmax && bi[k] > wi)) {
                    wmax = bd[k]; wi = bi[k]; wpos = k;
                }
        }
    }
    // merge across the 4 threads of this point (xor 1, then xor 2)
    #pragma unroll
    for (int st = 1; st <= 2; st <<= 1) {
        float od[KK]; int oi[KK];
        #pragma unroll
        for (int k = 0; k < KK; k++) {
            od[k] = __shfl_xor_sync(0xffffffffu, bd[k], st);
            oi[k] = __shfl_xor_sync(0xffffffffu, bi[k], st);
        }
        #pragma unroll
        for (int k2 = 0; k2 < KK; k2++) {
            float d = od[k2]; int i = oi[k2];
            if (d < wmax || (d == wmax && i < wi)) {
                #pragma unroll
                for (int k = 0; k < KK; k++)
                    if (k == wpos) { bd[k] = d; bi[k] = i; }
                wmax = bd[0]; wi = bi[0]; wpos = 0;
                #pragma unroll
                for (int k = 1; k < KK; k++)
                    if (bd[k] > wmax || (bd[k] == wmax && bi[k] > wi)) {
                        wmax = bd[k]; wi = bi[k]; wpos = k;
                    }
            }
        }
    }
    if (q == 0) {
        #pragma unroll
        for (int k = 0; k < KK; k++) g_idx[pt*KK + k] = bi[k];
    }
}

// ---------------- K3: edge MLP layer-2 on tensor cores ----------------
#define ESA_HI 0
#define ESA_LO (144*ROW_W)
#define ESB_HI (2*144*ROW_W)
#define ESB_LO (2*144*ROW_W + 128*ROW_W)
#define ESM_WORDS (2*144*ROW_W + 2*128*ROW_W)

__global__ void __launch_bounds__(256) k_edge(
    const float* __restrict__ W2, const float* __restrict__ b2)
{
    extern __shared__ __align__(16) uint32_t esm[];
    int tid = threadIdx.x;
    int base = blockIdx.x * 16;
    int w = tid >> 5, lane = tid & 31;

    // stage W2^T: row c' holds W2[:, c'] (col-major B operand), hi/lo split
    for (int idx = tid; idx < 128*64; idx += 256) {
        int cp = idx & 127;
        int cw = idx >> 7;
        float w0 = W2[(2*cw)*CC + cp];
        float w1 = W2[(2*cw+1)*CC + cp];
        __nv_bfloat16 h0 = __float2bfloat16_rn(w0);
        __nv_bfloat16 h1 = __float2bfloat16_rn(w1);
        esm[ESB_HI + cp*ROW_W + cw] = pack_bf16x2(w0, w1);
        esm[ESB_LO + cp*ROW_W + cw] =
            pack_bf16x2(w0 - __bfloat162float(h0), w1 - __bfloat162float(h1));
    }

    // stage H rows: warp w builds rows [18w, 18w+18)
    #pragma unroll 2
    for (int ri = 0; ri < 18; ri++) {
        int r = w*18 + ri;
        int p = r / 9, kk = r - p*9;
        int pt = base + p;
        float4 u4 = *(const float4*)&g_u[pt*CC + lane*4];
        float4 v4 = *(const float4*)&g_v[pt*CC + lane*4];
        int nb = g_idx[pt*KK + kk];
        float4 gv = *(const float4*)&g_v[nb*CC + lane*4];
        float h0 = u4.x - v4.x + gv.x; h0 = h0 >= 0.f ? h0 : 0.2f*h0;
        float h1 = u4.y - v4.y + gv.y; h1 = h1 >= 0.f ? h1 : 0.2f*h1;
        float h2 = u4.z - v4.z + gv.z; h2 = h2 >= 0.f ? h2 : 0.2f*h2;
        float h3 = u4.w - v4.w + gv.w; h3 = h3 >= 0.f ? h3 : 0.2f*h3;
        __nv_bfloat16 t0 = __float2bfloat16_rn(h0);
        __nv_bfloat16 t1 = __float2bfloat16_rn(h1);
        __nv_bfloat16 t2 = __float2bfloat16_rn(h2);
        __nv_bfloat16 t3 = __float2bfloat16_rn(h3);
        *(uint2*)&esm[ESA_HI + r*ROW_W + lane*2] =
            make_uint2(pack_bf16x2(h0, h1), pack_bf16x2(h2, h3));
        *(uint2*)&esm[ESA_LO + r*ROW_W + lane*2] =
            make_uint2(pack_bf16x2(h0 - __bfloat162float(t0), h1 - __bfloat162float(t1)),
                       pack_bf16x2(h2 - __bfloat162float(t2), h3 - __bfloat162float(t3)));
    }
    __syncthreads();

    int g = lane >> 2, tq = lane & 3;
    int nbase = w*16;

    float mx[2][4];
    #pragma unroll
    for (int nt = 0; nt < 2; nt++)
        #pragma unroll
        for (int i = 0; i < 4; i++) mx[nt][i] = -3.4e38f;

    #pragma unroll
    for (int kk = 0; kk < KK; kk++) {
        float acc[2][4];
        #pragma unroll
        for (int nt = 0; nt < 2; nt++)
            #pragma unroll
            for (int i = 0; i < 4; i++) acc[nt][i] = 0.f;
        int r0 = g*9 + kk, r1 = (g+8)*9 + kk;
        #pragma unroll
        for (int kt = 0; kt < 8; kt++) {
            int kw = kt*8 + tq;
            uint32_t ah[4], al[4];
            ah[0] = esm[ESA_HI + r0*ROW_W + kw  ];
            ah[1] = esm[ESA_HI + r1*ROW_W + kw  ];
            ah[2] = esm[ESA_HI + r0*ROW_W + kw+4];
            ah[3] = esm[ESA_HI + r1*ROW_W + kw+4];
            al[0] = esm[ESA_LO + r0*ROW_W + kw  ];
            al[1] = esm[ESA_LO + r1*ROW_W + kw  ];
            al[2] = esm[ESA_LO + r0*ROW_W + kw+4];
            al[3] = esm[ESA_LO + r1*ROW_W + kw+4];
            #pragma unroll
            for (int nt = 0; nt < 2; nt++) {
                int br = nbase + nt*8 + g;
                uint32_t bh[2], bl[2];
                bh[0] = esm[ESB_HI + br*ROW_W + kw  ];
                bh[1] = esm[ESB_HI + br*ROW_W + kw+4];
                bl[0] = esm[ESB_LO + br*ROW_W + kw  ];
                bl[1] = esm[ESB_LO + br*ROW_W + kw+4];
                mma16816(acc[nt], ah, bh);
                mma16816(acc[nt], ah, bl);
                mma16816(acc[nt], al, bh);
            }
        }
        #pragma unroll
        for (int nt = 0; nt < 2; nt++)
            #pragma unroll
            for (int i = 0; i < 4; i++) mx[nt][i] = fmaxf(mx[nt][i], acc[nt][i]);
    }

    int p0 = base + g, p1 = base + g + 8;
    #pragma unroll
    for (int nt = 0; nt < 2; nt++) {
        int c = nbase + nt*8 + tq*2;
        float bb0 = b2[c], bb1 = b2[c+1];
        *(float2*)&g_pre[p0*CC + c] = make_float2(mx[nt][0] + bb0, mx[nt][1] + bb1);
        *(float2*)&g_pre[p1*CC + c] = make_float2(mx[nt][2] + bb0, mx[nt][3] + bb1);
    }
}

// ---------------- K3b: BN statistics (coalesced scan of g_pre) ----------------
__global__ void __launch_bounds__(256) k_stats()
{
    __shared__ float ss[128], qs[128];
    int t = threadIdx.x, c = t & 127, half = t >> 7;
    int p0 = blockIdx.x * 128 + half*64;
    float s = 0.f, q = 0.f;
    #pragma unroll 4
    for (int p = 0; p < 64; p++) {
        float v = g_pre[(p0 + p)*CC + c];
        s += v; q += v*v;
    }
    if (half) { ss[c] = s; qs[c] = q; }
    __syncthreads();
    if (!half) {
        s += ss[c]; q += qs[c];
        atomicAdd(&g_dsum[c], (double)s);
        atomicAdd(&g_dsqs[c], (double)q);
    }
}

// ---------------- K4: BN scale/shift ----------------
__global__ void k_bn(const float* __restrict__ gamma, const float* __restrict__ beta)
{
    int j = threadIdx.x;
    const double inv = 1.0 / (double)(BB*NN);
    double mean = g_dsum[j] * inv;
    double var  = g_dsqs[j] * inv - mean*mean;
    float sc = gamma[j] * rsqrtf((float)var + 1e-5f);
    g_scale[j] = sc;
    g_shift[j] = beta[j] - (float)mean * sc;
}

// ---------------- K5: transpose + BN apply + residual + ReLU ----------------
__global__ void __launch_bounds__(256) k_apply(
    const float* __restrict__ x, float* __restrict__ out)
{
    __shared__ float tile[32][33];
    int b  = blockIdx.z;
    int c0 = blockIdx.y * 32;
    int n0 = blockIdx.x * 32;
    int t = threadIdx.x;
    int cj = t & 31, i0 = t >> 5;

    for (int i = i0; i < 32; i += 8)
        tile[i][cj] = g_pre[((b*NN) + n0 + i)*CC + c0 + cj];
    __syncthreads();

    int nj = t & 31;
    for (int ci = i0; ci < 32; ci += 8) {
        int c = c0 + ci;
        int o = (b*CC + c)*NN + n0 + nj;
        float v = tile[nj][ci] * g_scale[c] + g_shift[c] + x[o];
        out[o] = v > 0.f ? v : 0.f;
    }
}

// ---------------- launch ----------------
#define GSM_BYTES (4*128*ROW_W*4 + 128*4)   // tiles + sqm
#define ESM_BYTES (ESM_WORDS*4)             // k_edge smem (147968)

extern "C" void kernel_launch(void* const* d_in, const int* in_sizes, int n_in,
                              void* d_out, int out_size)
{
    const float* x     = (const float*)d_in[0];
    const float* W1    = (const float*)d_in[1];
    const float* b1    = (const float*)d_in[2];
    const float* W2    = (const float*)d_in[3];
    const float* b2    = (const float*)d_in[4];
    const float* gamma = (const float*)d_in[5];
    const float* beta  = (const float*)d_in[6];
    float* out = (float*)d_out;

    cudaFuncSetAttribute(k_gram, cudaFuncAttributeMaxDynamicSharedMemorySize, GSM_BYTES);
    cudaFuncSetAttribute(k_edge, cudaFuncAttributeMaxDynamicSharedMemorySize, ESM_BYTES);

    k_init <<<1, 128>>>();
    k_point<<<NPT/16, 128>>>(x, W1, b1);
    k_gram <<<dim3(8, 8, BB), 256, GSM_BYTES>>>(x);
    k_topk <<<dim3(NN/256, BB, NCH), 256>>>();
    k_merge<<<NPT/64, 256>>>();
    k_edge <<<NPT/16, 256, ESM_BYTES>>>(W2, b2);
    k_stats<<<NPT/128, 256>>>();
    k_bn   <<<1, 128>>>(gamma, beta);
    k_apply<<<dim3(NN/32, CC/32, BB), 256>>>(x, out);
}

// round 16
// speedup vs baseline: 2.2824x; 1.0012x over previous
#include <cuda_runtime.h>
#include <cuda_bf16.h>
#include <cstdint>

#define BB 16
#define CC 128
#define NN 1024
#define KK 9
#define NCH 16           // topk m-chunks
#define MCH (NN/NCH)     // 64 m per chunk
#define NPT (BB*NN)      // 16384 points
#define ROW_W 68         // smem row stride in 32-bit words (64 data + 4 pad)

// ---- scratch (device globals; no allocation allowed) ----
__device__ float  g_sq[NPT];
__device__ float  g_u[NPT*CC];
__device__ float  g_v[NPT*CC];
__device__ int    g_idx[NPT*KK];
__device__ float  g_pre[NPT*CC];
__device__ float  g_dot[(size_t)NPT*NN];   // 67MB: key[b][n][m] = sq_m - 2*dot
__device__ float  g_cd[NCH*KK*NPT];
__device__ int    g_ci[NCH*KK*NPT];
__device__ double g_dsum[CC];
__device__ double g_dsqs[CC];
__device__ float  g_scale[CC];
__device__ float  g_shift[CC];

// warp-level bf16 MMA (PTX ISA 7.0+, compiles on compute_103 -> HMMA)
__device__ __forceinline__ void mma16816(float* c, const uint32_t* a, const uint32_t* b) {
    asm volatile(
        "mma.sync.aligned.m16n8k16.row.col.f32.bf16.bf16.f32 "
        "{%0,%1,%2,%3}, {%4,%5,%6,%7}, {%8,%9}, {%0,%1,%2,%3};"
        : "+f"(c[0]), "+f"(c[1]), "+f"(c[2]), "+f"(c[3])
        : "r"(a[0]), "r"(a[1]), "r"(a[2]), "r"(a[3]), "r"(b[0]), "r"(b[1]));
}

__device__ __forceinline__ uint32_t pack_bf16x2(float f0, float f1) {
    __nv_bfloat162 t = __floats2bfloat162_rn(f0, f1);
    return *reinterpret_cast<uint32_t*>(&t);
}

// ---------------- K0 ----------------
__global__ void k_init() {
    int t = threadIdx.x;
    g_dsum[t] = 0.0; g_dsqs[t] = 0.0;
}

// ---------------- K1: per-point sq, u, v via mma.sync ----------------
// Block: 128 points, 256 thr. grp0 stages x (A, 128 rows) + computes sq;
// grp1 stages W1^T as B: rows 0..127 = u weights (W1[c][j]), rows 128..255 =
// v weights (W1[128+c][j]). Warp w: A rows [16w,16w+16), 2 phases (u, v).
#define PSA_HI 0
#define PSA_LO (128*ROW_W)
#define PSB_HI (2*128*ROW_W)
#define PSB_LO (2*128*ROW_W + 256*ROW_W)
#define PSM_WORDS (2*128*ROW_W + 2*256*ROW_W)

__global__ void __launch_bounds__(256) k_pt(
    const float* __restrict__ x, const float* __restrict__ W1,
    const float* __restrict__ b1)
{
    extern __shared__ __align__(16) uint32_t psm[];
    int tid = threadIdx.x;
    int grp = tid >> 7, t = tid & 127;
    int base = blockIdx.x * 128;
    int b = base / NN, n0 = base % NN;

    if (grp == 0) {
        // stage x point (base+t): all 128 channels, hi/lo split; sq for free
        const float* xb = x + (size_t)b*CC*NN + n0 + t;
        float s = 0.f;
        #pragma unroll 8
        for (int c = 0; c < CC; c += 2) {
            float v0 = xb[(size_t)c*NN];
            float v1 = xb[(size_t)(c+1)*NN];
            s += v0*v0 + v1*v1;
            __nv_bfloat16 h0 = __float2bfloat16_rn(v0);
            __nv_bfloat16 h1 = __float2bfloat16_rn(v1);
            psm[PSA_HI + t*ROW_W + (c>>1)] = pack_bf16x2(v0, v1);
            psm[PSA_LO + t*ROW_W + (c>>1)] =
                pack_bf16x2(v0 - __bfloat162float(h0), v1 - __bfloat162float(h1));
        }
        g_sq[base + t] = s;
    } else {
        // stage W1^T rows t (u) and 128+t (v); coalesced over t
        #pragma unroll 4
        for (int cw = 0; cw < 64; cw++) {
            float wu0 = W1[(2*cw  )*CC + t];
            float wu1 = W1[(2*cw+1)*CC + t];
            float wv0 = W1[(CC+2*cw  )*CC + t];
            float wv1 = W1[(CC+2*cw+1)*CC + t];
            __nv_bfloat16 a0 = __float2bfloat16_rn(wu0);
            __nv_bfloat16 a1 = __float2bfloat16_rn(wu1);
            __nv_bfloat16 c0 = __float2bfloat16_rn(wv0);
            __nv_bfloat16 c1 = __float2bfloat16_rn(wv1);
            psm[PSB_HI + t*ROW_W + cw] = pack_bf16x2(wu0, wu1);
            psm[PSB_LO + t*ROW_W + cw] =
                pack_bf16x2(wu0 - __bfloat162float(a0), wu1 - __bfloat162float(a1));
            psm[PSB_HI + (128+t)*ROW_W + cw] = pack_bf16x2(wv0, wv1);
            psm[PSB_LO + (128+t)*ROW_W + cw] =
                pack_bf16x2(wv0 - __bfloat162float(c0), wv1 - __bfloat162float(c1));
        }
    }
    __syncthreads();

    int w = tid >> 5, lane = tid & 31;
    int g = lane >> 2, tq = lane & 3;
    int ar = w*16 + g;

    #pragma unroll
    for (int ph = 0; ph < 2; ph++) {
        float acc[16][4];
        #pragma unroll
        for (int i = 0; i < 16; i++) { acc[i][0]=acc[i][1]=acc[i][2]=acc[i][3]=0.f; }
        #pragma unroll
        for (int kt = 0; kt < 8; kt++) {
            int kw = kt*8 + tq;
            uint32_t ah[4], al[4];
            ah[0] = psm[PSA_HI +  ar   *ROW_W + kw  ];
            ah[1] = psm[PSA_HI + (ar+8)*ROW_W + kw  ];
            ah[2] = psm[PSA_HI +  ar   *ROW_W + kw+4];
            ah[3] = psm[PSA_HI + (ar+8)*ROW_W + kw+4];
            al[0] = psm[PSA_LO +  ar   *ROW_W + kw  ];
            al[1] = psm[PSA_LO + (ar+8)*ROW_W + kw  ];
            al[2] = psm[PSA_LO +  ar   *ROW_W + kw+4];
            al[3] = psm[PSA_LO + (ar+8)*ROW_W + kw+4];
            #pragma unroll
            for (int bt = 0; bt < 16; bt++) {
                int br = ph*128 + bt*8 + g;
                uint32_t bh[2], bl[2];
                bh[0] = psm[PSB_HI + br*ROW_W + kw  ];
                bh[1] = psm[PSB_HI + br*ROW_W + kw+4];
                bl[0] = psm[PSB_LO + br*ROW_W + kw  ];
                bl[1] = psm[PSB_LO + br*ROW_W + kw+4];
                mma16816(acc[bt], ah, bh);
                mma16816(acc[bt], ah, bl);
                mma16816(acc[bt], al, bh);
            }
        }
        int p0 = base + ar, p1 = base + ar + 8;
        float* dst = ph ? g_v : g_u;
        #pragma unroll
        for (int bt = 0; bt < 16; bt++) {
            int c = bt*8 + tq*2;
            float bb0 = ph ? 0.f : b1[c];
            float bb1 = ph ? 0.f : b1[c+1];
            *(float2*)&dst[p0*CC + c] = make_float2(acc[bt][0] + bb0, acc[bt][1] + bb1);
            *(float2*)&dst[p1*CC + c] = make_float2(acc[bt][2] + bb0, acc[bt][3] + bb1);
        }
    }
}

// ---------------- K2a: tensor gram via mma.sync; epilogue stores key = sq_m - 2*dot ----------------
__global__ void __launch_bounds__(256) k_gram(const float* __restrict__ x)
{
    extern __shared__ __align__(16) uint32_t sm[];
    uint32_t* SA_HI = sm;
    uint32_t* SA_LO = sm + 128*ROW_W;
    uint32_t* SB_HI = sm + 2*128*ROW_W;
    uint32_t* SB_LO = sm + 3*128*ROW_W;
    float*    sqm   = (float*)(sm + 4*128*ROW_W);   // 128 floats

    int tid = threadIdx.x;
    int b  = blockIdx.z;
    int n0 = blockIdx.x * 128, m0 = blockIdx.y * 128;

    {
        int grp = tid >> 7;
        int t   = tid & 127;
        int off = grp ? m0 : n0;
        uint32_t* HI = grp ? SB_HI : SA_HI;
        uint32_t* LO = grp ? SB_LO : SA_LO;
        const float* xb = x + (size_t)b*CC*NN + off + t;
        #pragma unroll 8
        for (int c = 0; c < CC; c += 2) {
            float v0 = xb[(size_t)c*NN];
            float v1 = xb[(size_t)(c+1)*NN];
            __nv_bfloat16 h0 = __float2bfloat16_rn(v0);
            __nv_bfloat16 h1 = __float2bfloat16_rn(v1);
            HI[t*ROW_W + (c>>1)] = pack_bf16x2(v0, v1);
            LO[t*ROW_W + (c>>1)] =
                pack_bf16x2(v0 - __bfloat162float(h0), v1 - __bfloat162float(h1));
        }
    }
    if (tid < 128) sqm[tid] = g_sq[b*NN + m0 + tid];
    __syncthreads();

    int w = tid >> 5, lane = tid & 31;
    int g = lane >> 2, tq = lane & 3;
    int ar = w*16 + g;

    float acc[16][4];
    #pragma unroll
    for (int i = 0; i < 16; i++) { acc[i][0]=acc[i][1]=acc[i][2]=acc[i][3]=0.f; }

    #pragma unroll
    for (int kt = 0; kt < 8; kt++) {
        int kw = kt*8 + tq;
        uint32_t ah[4], al[4];
        ah[0] = SA_HI[ ar     *ROW_W + kw  ];
        ah[1] = SA_HI[(ar+8)  *ROW_W + kw  ];
        ah[2] = SA_HI[ ar     *ROW_W + kw+4];
        ah[3] = SA_HI[(ar+8)  *ROW_W + kw+4];
        al[0] = SA_LO[ ar     *ROW_W + kw  ];
        al[1] = SA_LO[(ar+8)  *ROW_W + kw  ];
        al[2] = SA_LO[ ar     *ROW_W + kw+4];
        al[3] = SA_LO[(ar+8)  *ROW_W + kw+4];
        #pragma unroll
        for (int bt = 0; bt < 16; bt++) {
            int br = bt*8 + g;
            uint32_t bh[2], bl[2];
            bh[0] = SB_HI[br*ROW_W + kw  ];
            bh[1] = SB_HI[br*ROW_W + kw+4];
            bl[0] = SB_LO[br*ROW_W + kw  ];
            bl[1] = SB_LO[br*ROW_W + kw+4];
            mma16816(acc[bt], ah, bh);   // hi*hi
            mma16816(acc[bt], ah, bl);   // hi*lo
            mma16816(acc[bt], al, bh);   // lo*hi
        }
    }

    int arow = n0 + w*16 + g;
    #pragma unroll
    for (int bt = 0; bt < 16; bt++) {
        int mloc = bt*8 + tq*2;
        int m = m0 + mloc;
        float s0 = sqm[mloc], s1 = sqm[mloc+1];
        float2 v01 = make_float2(fmaf(-2.f, acc[bt][0], s0), fmaf(-2.f, acc[bt][1], s1));
        float2 v23 = make_float2(fmaf(-2.f, acc[bt][2], s0), fmaf(-2.f, acc[bt][3], s1));
        *(float2*)&g_dot[(size_t)(b*NN + arow    )*NN + m] = v01;
        *(float2*)&g_dot[(size_t)(b*NN + arow + 8)*NN + m] = v23;
    }
}

// ---------------- K2b: chunked top-9, contiguous float4 row scan of keys ----------------
__global__ void __launch_bounds__(256) k_topk()
{
    int n  = blockIdx.x * 256 + threadIdx.x;
    int b  = blockIdx.y;
    int ch = blockIdx.z;
    int pt = b*NN + n;

    float bd[KK]; int bi[KK];
    #pragma unroll
    for (int k = 0; k < KK; k++) { bd[k] = 3.4e38f; bi[k] = 0; }
    float wmax = 3.4e38f; int wpos = 0;

    int mbase = ch*MCH;
    const float4* row = (const float4*)(g_dot + (size_t)pt*NN + mbase);
    #pragma unroll 8
    for (int i = 0; i < MCH/4; i++) {
        float4 v4 = row[i];
        float vv[4] = {v4.x, v4.y, v4.z, v4.w};
        #pragma unroll
        for (int q = 0; q < 4; q++) {
            float d2v = vv[q];
            int m = mbase + i*4 + q;
            if (d2v < wmax) {
                #pragma unroll
                for (int k = 0; k < KK; k++)
                    if (k == wpos) { bd[k] = d2v; bi[k] = m; }
                wmax = bd[0]; wpos = 0;
                #pragma unroll
                for (int k = 1; k < KK; k++)
                    if (bd[k] > wmax) { wmax = bd[k]; wpos = k; }
            }
        }
    }
    #pragma unroll
    for (int k = 0; k < KK; k++) {
        int slot = ch*KK + k;
        g_cd[slot*NPT + pt] = bd[k];
        g_ci[slot*NPT + pt] = b*NN + bi[k];
    }
}

// ---------------- K2c: merge 144 slots -> top-9; 8 threads/point + shfl merge ----------------
__global__ void __launch_bounds__(256) k_merge()
{
    int tid = threadIdx.x;
    int q   = tid & 7;
    int pt  = blockIdx.x * 32 + (tid >> 3);

    float bd[KK]; int bi[KK];
    #pragma unroll
    for (int k = 0; k < KK; k++) { bd[k] = 3.4e38f; bi[k] = 0x7fffffff; }
    float wmax = 3.4e38f; int wi = 0x7fffffff; int wpos = 0;

    #pragma unroll 2
    for (int s = q; s < NCH*KK; s += 8) {   // 18 slots each
        float d = g_cd[s*NPT + pt];
        int   i = g_ci[s*NPT + pt];
        if (d < wmax || (d == wmax && i < wi)) {
            #pragma unroll
            for (int k = 0; k < KK; k++)
                if (k == wpos) { bd[k] = d; bi[k] = i; }
            wmax = bd[0]; wi = bi[0]; wpos = 0;
            #pragma unroll
            for (int k = 1; k < KK; k++)
                if (bd[k] > wmax || (bd[k] == wmax && bi[k] > wi)) {
                    wmax = bd[k]; wi = bi[k]; wpos = k;
                }
        }
    }
    // merge across the 8 threads of this point (xor 1, 2, 4)
    #pragma unroll
    for (int st = 1; st <= 4; st <<= 1) {
        float od[KK]; int oi[KK];
        #pragma unroll
        for (int k = 0; k < KK; k++) {
            od[k] = __shfl_xor_sync(0xffffffffu, bd[k], st);
            oi[k] = __shfl_xor_sync(0xffffffffu, bi[k], st);
        }
        #pragma unroll
        for (int k2 = 0; k2 < KK; k2++) {
            float d = od[k2]; int i = oi[k2];
            if (d < wmax || (d == wmax && i < wi)) {
                #pragma unroll
                for (int k = 0; k < KK; k++)
                    if (k == wpos) { bd[k] = d; bi[k] = i; }
                wmax = bd[0]; wi = bi[0]; wpos = 0;
                #pragma unroll
                for (int k = 1; k < KK; k++)
                    if (bd[k] > wmax || (bd[k] == wmax && bi[k] > wi)) {
                        wmax = bd[k]; wi = bi[k]; wpos = k;
                    }
            }
        }
    }
    if (q == 0) {
        #pragma unroll
        for (int k = 0; k < KK; k++) g_idx[pt*KK + k] = bi[k];
    }
}

// ---------------- K3: edge MLP layer-2 on tensor cores ----------------
#define ESA_HI 0
#define ESA_LO (144*ROW_W)
#define ESB_HI (2*144*ROW_W)
#define ESB_LO (2*144*ROW_W + 128*ROW_W)
#define ESM_WORDS (2*144*ROW_W + 2*128*ROW_W)

__global__ void __launch_bounds__(256) k_edge(
    const float* __restrict__ W2, const float* __restrict__ b2)
{
    extern __shared__ __align__(16) uint32_t esm[];
    int tid = threadIdx.x;
    int base = blockIdx.x * 16;
    int w = tid >> 5, lane = tid & 31;

    // stage W2^T: row c' holds W2[:, c'] (col-major B operand), hi/lo split
    for (int idx = tid; idx < 128*64; idx += 256) {
        int cp = idx & 127;
        int cw = idx >> 7;
        float w0 = W2[(2*cw)*CC + cp];
        float w1 = W2[(2*cw+1)*CC + cp];
        __nv_bfloat16 h0 = __float2bfloat16_rn(w0);
        __nv_bfloat16 h1 = __float2bfloat16_rn(w1);
        esm[ESB_HI + cp*ROW_W + cw] = pack_bf16x2(w0, w1);
        esm[ESB_LO + cp*ROW_W + cw] =
            pack_bf16x2(w0 - __bfloat162float(h0), w1 - __bfloat162float(h1));
    }

    // stage H rows: warp w builds rows [18w, 18w+18)
    #pragma unroll 2
    for (int ri = 0; ri < 18; ri++) {
        int r = w*18 + ri;
        int p = r / 9, kk = r - p*9;
        int pt = base + p;
        float4 u4 = *(const float4*)&g_u[pt*CC + lane*4];
        float4 v4 = *(const float4*)&g_v[pt*CC + lane*4];
        int nb = g_idx[pt*KK + kk];
        float4 gv = *(const float4*)&g_v[nb*CC + lane*4];
        float h0 = u4.x - v4.x + gv.x; h0 = h0 >= 0.f ? h0 : 0.2f*h0;
        float h1 = u4.y - v4.y + gv.y; h1 = h1 >= 0.f ? h1 : 0.2f*h1;
        float h2 = u4.z - v4.z + gv.z; h2 = h2 >= 0.f ? h2 : 0.2f*h2;
        float h3 = u4.w - v4.w + gv.w; h3 = h3 >= 0.f ? h3 : 0.2f*h3;
        __nv_bfloat16 t0 = __float2bfloat16_rn(h0);
        __nv_bfloat16 t1 = __float2bfloat16_rn(h1);
        __nv_bfloat16 t2 = __float2bfloat16_rn(h2);
        __nv_bfloat16 t3 = __float2bfloat16_rn(h3);
        *(uint2*)&esm[ESA_HI + r*ROW_W + lane*2] =
            make_uint2(pack_bf16x2(h0, h1), pack_bf16x2(h2, h3));
        *(uint2*)&esm[ESA_LO + r*ROW_W + lane*2] =
            make_uint2(pack_bf16x2(h0 - __bfloat162float(t0), h1 - __bfloat162float(t1)),
                       pack_bf16x2(h2 - __bfloat162float(t2), h3 - __bfloat162float(t3)));
    }
    __syncthreads();

    int g = lane >> 2, tq = lane & 3;
    int nbase = w*16;

    float mx[2][4];
    #pragma unroll
    for (int nt = 0; nt < 2; nt++)
        #pragma unroll
        for (int i = 0; i < 4; i++) mx[nt][i] = -3.4e38f;

    #pragma unroll
    for (int kk = 0; kk < KK; kk++) {
        float acc[2][4];
        #pragma unroll
        for (int nt = 0; nt < 2; nt++)
            #pragma unroll
            for (int i = 0; i < 4; i++) acc[nt][i] = 0.f;
        int r0 = g*9 + kk, r1 = (g+8)*9 + kk;
        #pragma unroll
        for (int kt = 0; kt < 8; kt++) {
            int kw = kt*8 + tq;
            uint32_t ah[4], al[4];
            ah[0] = esm[ESA_HI + r0*ROW_W + kw  ];
            ah[1] = esm[ESA_HI + r1*ROW_W + kw  ];
            ah[2] = esm[ESA_HI + r0*ROW_W + kw+4];
            ah[3] = esm[ESA_HI + r1*ROW_W + kw+4];
            al[0] = esm[ESA_LO + r0*ROW_W + kw  ];
            al[1] = esm[ESA_LO + r1*ROW_W + kw  ];
            al[2] = esm[ESA_LO + r0*ROW_W + kw+4];
            al[3] = esm[ESA_LO + r1*ROW_W + kw+4];
            #pragma unroll
            for (int nt = 0; nt < 2; nt++) {
                int br = nbase + nt*8 + g;
                uint32_t bh[2], bl[2];
                bh[0] = esm[ESB_HI + br*ROW_W + kw  ];
                bh[1] = esm[ESB_HI + br*ROW_W + kw+4];
                bl[0] = esm[ESB_LO + br*ROW_W + kw  ];
                bl[1] = esm[ESB_LO + br*ROW_W + kw+4];
                mma16816(acc[nt], ah, bh);
                mma16816(acc[nt], ah, bl);
                mma16816(acc[nt], al, bh);
            }
        }
        #pragma unroll
        for (int nt = 0; nt < 2; nt++)
            #pragma unroll
            for (int i = 0; i < 4; i++) mx[nt][i] = fmaxf(mx[nt][i], acc[nt][i]);
    }

    int p0 = base + g, p1 = base + g + 8;
    #pragma unroll
    for (int nt = 0; nt < 2; nt++) {
        int c = nbase + nt*8 + tq*2;
        float bb0 = b2[c], bb1 = b2[c+1];
        *(float2*)&g_pre[p0*CC + c] = make_float2(mx[nt][0] + bb0, mx[nt][1] + bb1);
        *(float2*)&g_pre[p1*CC + c] = make_float2(mx[nt][2] + bb0, mx[nt][3] + bb1);
    }
}

// ---------------- K3b: BN statistics (coalesced scan of g_pre) ----------------
__global__ void __launch_bounds__(256) k_stats()
{
    __shared__ float ss[128], qs[128];
    int t = threadIdx.x, c = t & 127, half = t >> 7;
    int p0 = blockIdx.x * 128 + half*64;
    float s = 0.f, q = 0.f;
    #pragma unroll 4
    for (int p = 0; p < 64; p++) {
        float v = g_pre[(p0 + p)*CC + c];
        s += v; q += v*v;
    }
    if (half) { ss[c] = s; qs[c] = q; }
    __syncthreads();
    if (!half) {
        s += ss[c]; q += qs[c];
        atomicAdd(&g_dsum[c], (double)s);
        atomicAdd(&g_dsqs[c], (double)q);
    }
}

// ---------------- K4: BN scale/shift ----------------
__global__ void k_bn(const float* __restrict__ gamma, const float* __restrict__ beta)
{
    int j = threadIdx.x;
    const double inv = 1.0 / (double)(BB*NN);
    double mean = g_dsum[j] * inv;
    double var  = g_dsqs[j] * inv - mean*mean;
    float sc = gamma[j] * rsqrtf((float)var + 1e-5f);
    g_scale[j] = sc;
    g_shift[j] = beta[j] - (float)mean * sc;
}

// ---------------- K5: transpose + BN apply + residual + ReLU ----------------
__global__ void __launch_bounds__(256) k_apply(
    const float* __restrict__ x, float* __restrict__ out)
{
    __shared__ float tile[32][33];
    int b  = blockIdx.z;
    int c0 = blockIdx.y * 32;
    int n0 = blockIdx.x * 32;
    int t = threadIdx.x;
    int cj = t & 31, i0 = t >> 5;

    for (int i = i0; i < 32; i += 8)
        tile[i][cj] = g_pre[((b*NN) + n0 + i)*CC + c0 + cj];
    __syncthreads();

    int nj = t & 31;
    for (int ci = i0; ci < 32; ci += 8) {
        int c = c0 + ci;
        int o = (b*CC + c)*NN + n0 + nj;
        float v = tile[nj][ci] * g_scale[c] + g_shift[c] + x[o];
        out[o] = v > 0.f ? v : 0.f;
    }
}

// ---------------- launch ----------------
#define GSM_BYTES (4*128*ROW_W*4 + 128*4)   // k_gram: tiles + sqm
#define ESM_BYTES (ESM_WORDS*4)             // k_edge smem (147968)
#define PSM_BYTES (PSM_WORDS*4)             // k_pt smem (208896)

extern "C" void kernel_launch(void* const* d_in, const int* in_sizes, int n_in,
                              void* d_out, int out_size)
{
    const float* x     = (const float*)d_in[0];
    const float* W1    = (const float*)d_in[1];
    const float* b1    = (const float*)d_in[2];
    const float* W2    = (const float*)d_in[3];
    const float* b2    = (const float*)d_in[4];
    const float* gamma = (const float*)d_in[5];
    const float* beta  = (const float*)d_in[6];
    float* out = (float*)d_out;

    cudaFuncSetAttribute(k_gram, cudaFuncAttributeMaxDynamicSharedMemorySize, GSM_BYTES);
    cudaFuncSetAttribute(k_edge, cudaFuncAttributeMaxDynamicSharedMemorySize, ESM_BYTES);
    cudaFuncSetAttribute(k_pt,   cudaFuncAttributeMaxDynamicSharedMemorySize, PSM_BYTES);

    k_init <<<1, 128>>>();
    k_pt   <<<NPT/128, 256, PSM_BYTES>>>(x, W1, b1);
    k_gram <<<dim3(8, 8, BB), 256, GSM_BYTES>>>(x);
    k_topk <<<dim3(NN/256, BB, NCH), 256>>>();
    k_merge<<<NPT/32, 256>>>();
    k_edge <<<NPT/16, 256, ESM_BYTES>>>(W2, b2);
    k_stats<<<NPT/128, 256>>>();
    k_bn   <<<1, 128>>>(gamma, beta);
    k_apply<<<dim3(NN/32, CC/32, BB), 256>>>(x, out);
}

// round 17
// speedup vs baseline: 2.3107x; 1.0124x over previous
#include <cuda_runtime.h>
#include <cuda_bf16.h>
#include <cstdint>

#define BB 16
#define CC 128
#define NN 1024
#define KK 9
#define NPT (BB*NN)      // 16384 points
#define ROW_W 68         // smem row stride in 32-bit words (64 data + 4 pad)
#define KP 132           // keys tile row stride in words (128 + 4 pad)

// ---- scratch (device globals; no allocation allowed) ----
__device__ float  g_sq[NPT];
__device__ float  g_u[NPT*CC];
__device__ float  g_v[NPT*CC];
__device__ int    g_idx[NPT*KK];
__device__ float  g_pre[NPT*CC];
__device__ double g_dsum[CC];
__device__ double g_dsqs[CC];
__device__ float  g_scale[CC];
__device__ float  g_shift[CC];

// warp-level bf16 MMA (PTX ISA 7.0+, compiles on compute_103 -> HMMA)
__device__ __forceinline__ void mma16816(float* c, const uint32_t* a, const uint32_t* b) {
    asm volatile(
        "mma.sync.aligned.m16n8k16.row.col.f32.bf16.bf16.f32 "
        "{%0,%1,%2,%3}, {%4,%5,%6,%7}, {%8,%9}, {%0,%1,%2,%3};"
        : "+f"(c[0]), "+f"(c[1]), "+f"(c[2]), "+f"(c[3])
        : "r"(a[0]), "r"(a[1]), "r"(a[2]), "r"(a[3]), "r"(b[0]), "r"(b[1]));
}

__device__ __forceinline__ uint32_t pack_bf16x2(float f0, float f1) {
    __nv_bfloat162 t = __floats2bfloat162_rn(f0, f1);
    return *reinterpret_cast<uint32_t*>(&t);
}

// ---------------- K0 ----------------
__global__ void k_init() {
    int t = threadIdx.x;
    g_dsum[t] = 0.0; g_dsqs[t] = 0.0;
}

// ---------------- K1: per-point sq, u, v via mma.sync ----------------
#define PSA_HI 0
#define PSA_LO (128*ROW_W)
#define PSB_HI (2*128*ROW_W)
#define PSB_LO (2*128*ROW_W + 256*ROW_W)
#define PSM_WORDS (2*128*ROW_W + 2*256*ROW_W)

__global__ void __launch_bounds__(256) k_pt(
    const float* __restrict__ x, const float* __restrict__ W1,
    const float* __restrict__ b1)
{
    extern __shared__ __align__(16) uint32_t psm[];
    int tid = threadIdx.x;
    int grp = tid >> 7, t = tid & 127;
    int base = blockIdx.x * 128;
    int b = base / NN, n0 = base % NN;

    if (grp == 0) {
        const float* xb = x + (size_t)b*CC*NN + n0 + t;
        float s = 0.f;
        #pragma unroll 8
        for (int c = 0; c < CC; c += 2) {
            float v0 = xb[(size_t)c*NN];
            float v1 = xb[(size_t)(c+1)*NN];
            s += v0*v0 + v1*v1;
            __nv_bfloat16 h0 = __float2bfloat16_rn(v0);
            __nv_bfloat16 h1 = __float2bfloat16_rn(v1);
            psm[PSA_HI + t*ROW_W + (c>>1)] = pack_bf16x2(v0, v1);
            psm[PSA_LO + t*ROW_W + (c>>1)] =
                pack_bf16x2(v0 - __bfloat162float(h0), v1 - __bfloat162float(h1));
        }
        g_sq[base + t] = s;
    } else {
        #pragma unroll 4
        for (int cw = 0; cw < 64; cw++) {
            float wu0 = W1[(2*cw  )*CC + t];
            float wu1 = W1[(2*cw+1)*CC + t];
            float wv0 = W1[(CC+2*cw  )*CC + t];
            float wv1 = W1[(CC+2*cw+1)*CC + t];
            __nv_bfloat16 a0 = __float2bfloat16_rn(wu0);
            __nv_bfloat16 a1 = __float2bfloat16_rn(wu1);
            __nv_bfloat16 c0 = __float2bfloat16_rn(wv0);
            __nv_bfloat16 c1 = __float2bfloat16_rn(wv1);
            psm[PSB_HI + t*ROW_W + cw] = pack_bf16x2(wu0, wu1);
            psm[PSB_LO + t*ROW_W + cw] =
                pack_bf16x2(wu0 - __bfloat162float(a0), wu1 - __bfloat162float(a1));
            psm[PSB_HI + (128+t)*ROW_W + cw] = pack_bf16x2(wv0, wv1);
            psm[PSB_LO + (128+t)*ROW_W + cw] =
                pack_bf16x2(wv0 - __bfloat162float(c0), wv1 - __bfloat162float(c1));
        }
    }
    __syncthreads();

    int w = tid >> 5, lane = tid & 31;
    int g = lane >> 2, tq = lane & 3;
    int ar = w*16 + g;

    #pragma unroll
    for (int ph = 0; ph < 2; ph++) {
        float acc[16][4];
        #pragma unroll
        for (int i = 0; i < 16; i++) { acc[i][0]=acc[i][1]=acc[i][2]=acc[i][3]=0.f; }
        #pragma unroll
        for (int kt = 0; kt < 8; kt++) {
            int kw = kt*8 + tq;
            uint32_t ah[4], al[4];
            ah[0] = psm[PSA_HI +  ar   *ROW_W + kw  ];
            ah[1] = psm[PSA_HI + (ar+8)*ROW_W + kw  ];
            ah[2] = psm[PSA_HI +  ar   *ROW_W + kw+4];
            ah[3] = psm[PSA_HI + (ar+8)*ROW_W + kw+4];
            al[0] = psm[PSA_LO +  ar   *ROW_W + kw  ];
            al[1] = psm[PSA_LO + (ar+8)*ROW_W + kw  ];
            al[2] = psm[PSA_LO +  ar   *ROW_W + kw+4];
            al[3] = psm[PSA_LO + (ar+8)*ROW_W + kw+4];
            #pragma unroll
            for (int bt = 0; bt < 16; bt++) {
                int br = ph*128 + bt*8 + g;
                uint32_t bh[2], bl[2];
                bh[0] = psm[PSB_HI + br*ROW_W + kw  ];
                bh[1] = psm[PSB_HI + br*ROW_W + kw+4];
                bl[0] = psm[PSB_LO + br*ROW_W + kw  ];
                bl[1] = psm[PSB_LO + br*ROW_W + kw+4];
                mma16816(acc[bt], ah, bh);
                mma16816(acc[bt], ah, bl);
                mma16816(acc[bt], al, bh);
            }
        }
        int p0 = base + ar, p1 = base + ar + 8;
        float* dst = ph ? g_v : g_u;
        #pragma unroll
        for (int bt = 0; bt < 16; bt++) {
            int c = bt*8 + tq*2;
            float bb0 = ph ? 0.f : b1[c];
            float bb1 = ph ? 0.f : b1[c+1];
            *(float2*)&dst[p0*CC + c] = make_float2(acc[bt][0] + bb0, acc[bt][1] + bb1);
            *(float2*)&dst[p1*CC + c] = make_float2(acc[bt][2] + bb0, acc[bt][3] + bb1);
        }
    }
}

// ---------------- K2: FUSED knn = tensor gram + in-smem top-9 ----------------
// One CTA per (n-block of 128, batch). Loops over 8 m-blocks:
//   stage B -> bar -> MMA -> keys(=sq_m-2*dot) to smem -> bar -> scan (2 thr/row).
// Persistent per-thread top-9 regs; final pair shfl merge writes g_idx directly.
#define FSA_HI 0
#define FSA_LO (128*ROW_W)
#define FSB_HI (2*128*ROW_W)
#define FSB_LO (3*128*ROW_W)
#define FKEYS  (4*128*ROW_W)
#define FSQM   (4*128*ROW_W + 128*KP)
#define FSM_WORDS (4*128*ROW_W + 128*KP + 128)

__global__ void __launch_bounds__(256) k_knn(const float* __restrict__ x)
{
    extern __shared__ __align__(16) uint32_t fsm[];
    float* keys = (float*)(fsm + FKEYS);
    float* sqm  = (float*)(fsm + FSQM);

    int tid = threadIdx.x;
    int b  = blockIdx.y;
    int n0 = blockIdx.x * 128;

    // stage A (the n-block) once: thread = (row, c-half)
    {
        int row = tid & 127, ch = tid >> 7;
        const float* xb = x + (size_t)b*CC*NN + n0 + row;
        #pragma unroll 8
        for (int i = 0; i < 32; i++) {
            int cw = ch*32 + i, c = cw*2;
            float v0 = xb[(size_t)c*NN];
            float v1 = xb[(size_t)(c+1)*NN];
            __nv_bfloat16 h0 = __float2bfloat16_rn(v0);
            __nv_bfloat16 h1 = __float2bfloat16_rn(v1);
            fsm[FSA_HI + row*ROW_W + cw] = pack_bf16x2(v0, v1);
            fsm[FSA_LO + row*ROW_W + cw] =
                pack_bf16x2(v0 - __bfloat162float(h0), v1 - __bfloat162float(h1));
        }
    }

    int w = tid >> 5, lane = tid & 31;
    int g = lane >> 2, tq = lane & 3;
    int ar = w*16 + g;
    int r = tid >> 1, q = tid & 1;     // scan role: 2 threads per row

    // persistent top-9 (strict < within thread; candidates ascend in m)
    float bd[KK]; int bi[KK];
    #pragma unroll
    for (int k = 0; k < KK; k++) { bd[k] = 3.4e38f; bi[k] = 0x7fffffff; }
    float wmax = 3.4e38f; int wi = 0x7fffffff; int wpos = 0;

    for (int mt = 0; mt < 8; mt++) {
        int m0 = mt*128;
        // stage B (m-block) + sqm
        {
            int row = tid & 127, ch = tid >> 7;
            const float* xb = x + (size_t)b*CC*NN + m0 + row;
            #pragma unroll 8
            for (int i = 0; i < 32; i++) {
                int cw = ch*32 + i, c = cw*2;
                float v0 = xb[(size_t)c*NN];
                float v1 = xb[(size_t)(c+1)*NN];
                __nv_bfloat16 h0 = __float2bfloat16_rn(v0);
                __nv_bfloat16 h1 = __float2bfloat16_rn(v1);
                fsm[FSB_HI + row*ROW_W + cw] = pack_bf16x2(v0, v1);
                fsm[FSB_LO + row*ROW_W + cw] =
                    pack_bf16x2(v0 - __bfloat162float(h0), v1 - __bfloat162float(h1));
            }
            if (tid < 128) sqm[tid] = g_sq[b*NN + m0 + tid];
        }
        __syncthreads();   // B+sqm ready; prev scan complete (program order)

        float acc[16][4];
        #pragma unroll
        for (int i = 0; i < 16; i++) { acc[i][0]=acc[i][1]=acc[i][2]=acc[i][3]=0.f; }
        #pragma unroll
        for (int kt = 0; kt < 8; kt++) {
            int kw = kt*8 + tq;
            uint32_t ah[4], al[4];
            ah[0] = fsm[FSA_HI +  ar   *ROW_W + kw  ];
            ah[1] = fsm[FSA_HI + (ar+8)*ROW_W + kw  ];
            ah[2] = fsm[FSA_HI +  ar   *ROW_W + kw+4];
            ah[3] = fsm[FSA_HI + (ar+8)*ROW_W + kw+4];
            al[0] = fsm[FSA_LO +  ar   *ROW_W + kw  ];
            al[1] = fsm[FSA_LO + (ar+8)*ROW_W + kw  ];
            al[2] = fsm[FSA_LO +  ar   *ROW_W + kw+4];
            al[3] = fsm[FSA_LO + (ar+8)*ROW_W + kw+4];
            #pragma unroll
            for (int bt = 0; bt < 16; bt++) {
                int br = bt*8 + g;
                uint32_t bh[2], bl[2];
                bh[0] = fsm[FSB_HI + br*ROW_W + kw  ];
                bh[1] = fsm[FSB_HI + br*ROW_W + kw+4];
                bl[0] = fsm[FSB_LO + br*ROW_W + kw  ];
                bl[1] = fsm[FSB_LO + br*ROW_W + kw+4];
                mma16816(acc[bt], ah, bh);   // hi*hi
                mma16816(acc[bt], ah, bl);   // hi*lo
                mma16816(acc[bt], al, bh);   // lo*hi
            }
        }
        // keys tile: key = sq_m - 2*dot (rank == d2 rank; sq_n is row-constant)
        #pragma unroll
        for (int bt = 0; bt < 16; bt++) {
            int mloc = bt*8 + tq*2;
            float s0 = sqm[mloc], s1 = sqm[mloc+1];
            *(float2*)&keys[ ar   *KP + mloc] =
                make_float2(fmaf(-2.f, acc[bt][0], s0), fmaf(-2.f, acc[bt][1], s1));
            *(float2*)&keys[(ar+8)*KP + mloc] =
                make_float2(fmaf(-2.f, acc[bt][2], s0), fmaf(-2.f, acc[bt][3], s1));
        }
        __syncthreads();   // keys ready

        // scan: thread (r, q) covers keys[r][64q .. 64q+63]
        const float4* krow = (const float4*)&keys[r*KP + q*64];
        int mg0 = b*NN + m0 + q*64;
        #pragma unroll 4
        for (int i = 0; i < 16; i++) {
            float4 v4 = krow[i];
            float vv[4] = {v4.x, v4.y, v4.z, v4.w};
            #pragma unroll
            for (int j = 0; j < 4; j++) {
                float d = vv[j];
                if (d < wmax) {
                    int m = mg0 + i*4 + j;
                    #pragma unroll
                    for (int k = 0; k < KK; k++)
                        if (k == wpos) { bd[k] = d; bi[k] = m; }
                    wmax = bd[0]; wi = bi[0]; wpos = 0;
                    #pragma unroll
                    for (int k = 1; k < KK; k++)
                        if (bd[k] > wmax || (bd[k] == wmax && bi[k] > wi)) {
                            wmax = bd[k]; wi = bi[k]; wpos = k;
                        }
                }
            }
        }
    }

    // pair merge (xor 1) with (key, idx)-lexicographic tie-break
    {
        float od[KK]; int oi[KK];
        #pragma unroll
        for (int k = 0; k < KK; k++) {
            od[k] = __shfl_xor_sync(0xffffffffu, bd[k], 1);
            oi[k] = __shfl_xor_sync(0xffffffffu, bi[k], 1);
        }
        #pragma unroll
        for (int k2 = 0; k2 < KK; k2++) {
            float d = od[k2]; int i = oi[k2];
            if (d < wmax || (d == wmax && i < wi)) {
                #pragma unroll
                for (int k = 0; k < KK; k++)
                    if (k == wpos) { bd[k] = d; bi[k] = i; }
                wmax = bd[0]; wi = bi[0]; wpos = 0;
                #pragma unroll
                for (int k = 1; k < KK; k++)
                    if (bd[k] > wmax || (bd[k] == wmax && bi[k] > wi)) {
                        wmax = bd[k]; wi = bi[k]; wpos = k;
                    }
            }
        }
    }
    if (q == 0) {
        int pt = b*NN + n0 + r;
        #pragma unroll
        for (int k = 0; k < KK; k++) g_idx[pt*KK + k] = bi[k];
    }
}

// ---------------- K3: edge MLP layer-2 on tensor cores ----------------
#define ESA_HI 0
#define ESA_LO (144*ROW_W)
#define ESB_HI (2*144*ROW_W)
#define ESB_LO (2*144*ROW_W + 128*ROW_W)
#define ESM_WORDS (2*144*ROW_W + 2*128*ROW_W)

__global__ void __launch_bounds__(256) k_edge(
    const float* __restrict__ W2, const float* __restrict__ b2)
{
    extern __shared__ __align__(16) uint32_t esm[];
    int tid = threadIdx.x;
    int base = blockIdx.x * 16;
    int w = tid >> 5, lane = tid & 31;

    for (int idx = tid; idx < 128*64; idx += 256) {
        int cp = idx & 127;
        int cw = idx >> 7;
        float w0 = W2[(2*cw)*CC + cp];
        float w1 = W2[(2*cw+1)*CC + cp];
        __nv_bfloat16 h0 = __float2bfloat16_rn(w0);
        __nv_bfloat16 h1 = __float2bfloat16_rn(w1);
        esm[ESB_HI + cp*ROW_W + cw] = pack_bf16x2(w0, w1);
        esm[ESB_LO + cp*ROW_W + cw] =
            pack_bf16x2(w0 - __bfloat162float(h0), w1 - __bfloat162float(h1));
    }

    #pragma unroll 2
    for (int ri = 0; ri < 18; ri++) {
        int r = w*18 + ri;
        int p = r / 9, kk = r - p*9;
        int pt = base + p;
        float4 u4 = *(const float4*)&g_u[pt*CC + lane*4];
        float4 v4 = *(const float4*)&g_v[pt*CC + lane*4];
        int nb = g_idx[pt*KK + kk];
        float4 gv = *(const float4*)&g_v[nb*CC + lane*4];
        float h0 = u4.x - v4.x + gv.x; h0 = h0 >= 0.f ? h0 : 0.2f*h0;
        float h1 = u4.y - v4.y + gv.y; h1 = h1 >= 0.f ? h1 : 0.2f*h1;
        float h2 = u4.z - v4.z + gv.z; h2 = h2 >= 0.f ? h2 : 0.2f*h2;
        float h3 = u4.w - v4.w + gv.w; h3 = h3 >= 0.f ? h3 : 0.2f*h3;
        __nv_bfloat16 t0 = __float2bfloat16_rn(h0);
        __nv_bfloat16 t1 = __float2bfloat16_rn(h1);
        __nv_bfloat16 t2 = __float2bfloat16_rn(h2);
        __nv_bfloat16 t3 = __float2bfloat16_rn(h3);
        *(uint2*)&esm[ESA_HI + r*ROW_W + lane*2] =
            make_uint2(pack_bf16x2(h0, h1), pack_bf16x2(h2, h3));
        *(uint2*)&esm[ESA_LO + r*ROW_W + lane*2] =
            make_uint2(pack_bf16x2(h0 - __bfloat162float(t0), h1 - __bfloat162float(t1)),
                       pack_bf16x2(h2 - __bfloat162float(t2), h3 - __bfloat162float(t3)));
    }
    __syncthreads();

    int g = lane >> 2, tq = lane & 3;
    int nbase = w*16;

    float mx[2][4];
    #pragma unroll
    for (int nt = 0; nt < 2; nt++)
        #pragma unroll
        for (int i = 0; i < 4; i++) mx[nt][i] = -3.4e38f;

    #pragma unroll
    for (int kk = 0; kk < KK; kk++) {
        float acc[2][4];
        #pragma unroll
        for (int nt = 0; nt < 2; nt++)
            #pragma unroll
            for (int i = 0; i < 4; i++) acc[nt][i] = 0.f;
        int r0 = g*9 + kk, r1 = (g+8)*9 + kk;
        #pragma unroll
        for (int kt = 0; kt < 8; kt++) {
            int kw = kt*8 + tq;
            uint32_t ah[4], al[4];
            ah[0] = esm[ESA_HI + r0*ROW_W + kw  ];
            ah[1] = esm[ESA_HI + r1*ROW_W + kw  ];
            ah[2] = esm[ESA_HI + r0*ROW_W + kw+4];
            ah[3] = esm[ESA_HI + r1*ROW_W + kw+4];
            al[0] = esm[ESA_LO + r0*ROW_W + kw  ];
            al[1] = esm[ESA_LO + r1*ROW_W + kw  ];
            al[2] = esm[ESA_LO + r0*ROW_W + kw+4];
            al[3] = esm[ESA_LO + r1*ROW_W + kw+4];
            #pragma unroll
            for (int nt = 0; nt < 2; nt++) {
                int br = nbase + nt*8 + g;
                uint32_t bh[2], bl[2];
                bh[0] = esm[ESB_HI + br*ROW_W + kw  ];
                bh[1] = esm[ESB_HI + br*ROW_W + kw+4];
                bl[0] = esm[ESB_LO + br*ROW_W + kw  ];
                bl[1] = esm[ESB_LO + br*ROW_W + kw+4];
                mma16816(acc[nt], ah, bh);
                mma16816(acc[nt], ah, bl);
                mma16816(acc[nt], al, bh);
            }
        }
        #pragma unroll
        for (int nt = 0; nt < 2; nt++)
            #pragma unroll
            for (int i = 0; i < 4; i++) mx[nt][i] = fmaxf(mx[nt][i], acc[nt][i]);
    }

    int p0 = base + g, p1 = base + g + 8;
    #pragma unroll
    for (int nt = 0; nt < 2; nt++) {
        int c = nbase + nt*8 + tq*2;
        float bb0 = b2[c], bb1 = b2[c+1];
        *(float2*)&g_pre[p0*CC + c] = make_float2(mx[nt][0] + bb0, mx[nt][1] + bb1);
        *(float2*)&g_pre[p1*CC + c] = make_float2(mx[nt][2] + bb0, mx[nt][3] + bb1);
    }
}

// ---------------- K3b: BN statistics (coalesced scan of g_pre) ----------------
__global__ void __launch_bounds__(256) k_stats()
{
    __shared__ float ss[128], qs[128];
    int t = threadIdx.x, c = t & 127, half = t >> 7;
    int p0 = blockIdx.x * 128 + half*64;
    float s = 0.f, q = 0.f;
    #pragma unroll 4
    for (int p = 0; p < 64; p++) {
        float v = g_pre[(p0 + p)*CC + c];
        s += v; q += v*v;
    }
    if (half) { ss[c] = s; qs[c] = q; }
    __syncthreads();
    if (!half) {
        s += ss[c]; q += qs[c];
        atomicAdd(&g_dsum[c], (double)s);
        atomicAdd(&g_dsqs[c], (double)q);
    }
}

// ---------------- K4: BN scale/shift ----------------
__global__ void k_bn(const float* __restrict__ gamma, const float* __restrict__ beta)
{
    int j = threadIdx.x;
    const double inv = 1.0 / (double)(BB*NN);
    double mean = g_dsum[j] * inv;
    double var  = g_dsqs[j] * inv - mean*mean;
    float sc = gamma[j] * rsqrtf((float)var + 1e-5f);
    g_scale[j] = sc;
    g_shift[j] = beta[j] - (float)mean * sc;
}

// ---------------- K5: transpose + BN apply + residual + ReLU ----------------
__global__ void __launch_bounds__(256) k_apply(
    const float* __restrict__ x, float* __restrict__ out)
{
    __shared__ float tile[32][33];
    int b  = blockIdx.z;
    int c0 = blockIdx.y * 32;
    int n0 = blockIdx.x * 32;
    int t = threadIdx.x;
    int cj = t & 31, i0 = t >> 5;

    for (int i = i0; i < 32; i += 8)
        tile[i][cj] = g_pre[((b*NN) + n0 + i)*CC + c0 + cj];
    __syncthreads();

    int nj = t & 31;
    for (int ci = i0; ci < 32; ci += 8) {
        int c = c0 + ci;
        int o = (b*CC + c)*NN + n0 + nj;
        float v = tile[nj][ci] * g_scale[c] + g_shift[c] + x[o];
        out[o] = v > 0.f ? v : 0.f;
    }
}

// ---------------- launch ----------------
#define FSM_BYTES (FSM_WORDS*4)   // fused knn smem (207360)
#define ESM_BYTES (ESM_WORDS*4)   // k_edge smem (147968)
#define PSM_BYTES (PSM_WORDS*4)   // k_pt smem (208896)

extern "C" void kernel_launch(void* const* d_in, const int* in_sizes, int n_in,
                              void* d_out, int out_size)
{
    const float* x     = (const float*)d_in[0];
    const float* W1    = (const float*)d_in[1];
    const float* b1    = (const float*)d_in[2];
    const float* W2    = (const float*)d_in[3];
    const float* b2    = (const float*)d_in[4];
    const float* gamma = (const float*)d_in[5];
    const float* beta  = (const float*)d_in[6];
    float* out = (float*)d_out;

    cudaFuncSetAttribute(k_knn,  cudaFuncAttributeMaxDynamicSharedMemorySize, FSM_BYTES);
    cudaFuncSetAttribute(k_edge, cudaFuncAttributeMaxDynamicSharedMemorySize, ESM_BYTES);
    cudaFuncSetAttribute(k_pt,   cudaFuncAttributeMaxDynamicSharedMemorySize, PSM_BYTES);

    k_init <<<1, 128>>>();
    k_pt   <<<NPT/128, 256, PSM_BYTES>>>(x, W1, b1);
    k_knn  <<<dim3(8, BB), 256, FSM_BYTES>>>(x);
    k_edge <<<NPT/16, 256, ESM_BYTES>>>(W2, b2);
    k_stats<<<NPT/128, 256>>>();
    k_bn   <<<1, 128>>>(gamma, beta);
    k_apply<<<dim3(NN/32, CC/32, BB), 256>>>(x, out);
}